// round 1
// baseline (speedup 1.0000x reference)
#include <cuda_runtime.h>

#define BB 2
#define SS 2048
#define DD 1024
#define HH 16
#define DK 64
#define MR (BB*SS)   // 4096 rows

// ---------------- scratch (device globals; no allocation allowed) ------------
__device__ float g_q[(size_t)MR * DD];
__device__ float g_k[(size_t)MR * DD];
__device__ float g_v[(size_t)MR * DD];
__device__ float g_attn[(size_t)MR * DD];

// ---------------- GEMM: C[M,1024] = A[M,1024] * W[1024,1024]^T + bias --------
// BM=BN=128, BK=16, 256 threads, 8x8 register tile (strided frags, pad-17 smem)
__global__ __launch_bounds__(256) void gemm_nt_bias(
    const float* __restrict__ A, const float* __restrict__ W,
    const float* __restrict__ bias, float* __restrict__ C)
{
    __shared__ float As[128][17];
    __shared__ float Ws[128][17];

    const int t  = threadIdx.x;
    const int tx = t & 15;
    const int ty = t >> 4;
    const int rowBase = blockIdx.y << 7;
    const int colBase = blockIdx.x << 7;

    const int lrow = t >> 2;        // 0..63
    const int lk   = (t & 3) << 2;  // 0,4,8,12

    const float* Ar0 = A + (size_t)(rowBase + lrow) * 1024 + lk;
    const float* Ar1 = Ar0 + (size_t)64 * 1024;
    const float* Wr0 = W + (size_t)(colBase + lrow) * 1024 + lk;
    const float* Wr1 = Wr0 + (size_t)64 * 1024;

    float acc[8][8];
    #pragma unroll
    for (int i = 0; i < 8; i++)
        #pragma unroll
        for (int j = 0; j < 8; j++) acc[i][j] = 0.0f;

    for (int k0 = 0; k0 < 1024; k0 += 16) {
        float4 a0 = *(const float4*)(Ar0 + k0);
        float4 a1 = *(const float4*)(Ar1 + k0);
        float4 w0 = *(const float4*)(Wr0 + k0);
        float4 w1 = *(const float4*)(Wr1 + k0);

        __syncthreads();   // previous compute done before overwriting smem
        As[lrow   ][lk+0] = a0.x; As[lrow   ][lk+1] = a0.y;
        As[lrow   ][lk+2] = a0.z; As[lrow   ][lk+3] = a0.w;
        As[lrow+64][lk+0] = a1.x; As[lrow+64][lk+1] = a1.y;
        As[lrow+64][lk+2] = a1.z; As[lrow+64][lk+3] = a1.w;
        Ws[lrow   ][lk+0] = w0.x; Ws[lrow   ][lk+1] = w0.y;
        Ws[lrow   ][lk+2] = w0.z; Ws[lrow   ][lk+3] = w0.w;
        Ws[lrow+64][lk+0] = w1.x; Ws[lrow+64][lk+1] = w1.y;
        Ws[lrow+64][lk+2] = w1.z; Ws[lrow+64][lk+3] = w1.w;
        __syncthreads();

        #pragma unroll
        for (int kk = 0; kk < 16; kk++) {
            float af[8], wf[8];
            #pragma unroll
            for (int i = 0; i < 8; i++) af[i] = As[ty + 16*i][kk];
            #pragma unroll
            for (int j = 0; j < 8; j++) wf[j] = Ws[tx + 16*j][kk];
            #pragma unroll
            for (int i = 0; i < 8; i++)
                #pragma unroll
                for (int j = 0; j < 8; j++)
                    acc[i][j] += af[i] * wf[j];
        }
    }

    #pragma unroll
    for (int i = 0; i < 8; i++) {
        const int r = rowBase + ty + 16*i;
        #pragma unroll
        for (int j = 0; j < 8; j++) {
            const int c = colBase + tx + 16*j;
            C[(size_t)r * 1024 + c] = acc[i][j] + bias[c];
        }
    }
}

// ---------------- Flash attention (causal), fp32 SIMT ------------------------
// grid = (S/64 q-tiles, B*H), 256 threads. BQ=BK=64, DK=64.
// Thread (ty,tx) owns rows {ty+16i} and cols {tx+16j} (i,j in 0..3).
// Qs and KsPs use rotation swizzle col' = (d+row)&63 for conflict-free reads.
// P tile is written back into the K tile buffer (phases separated by barriers).
__global__ __launch_bounds__(256) void flash_attn(
    const float* __restrict__ qb, const float* __restrict__ kb,
    const float* __restrict__ vb, float* __restrict__ ob)
{
    __shared__ float Qs[64 * 64];
    __shared__ float KsPs[64 * 64];
    __shared__ float Vs[64 * 64];

    const int t  = threadIdx.x;
    const int tx = t & 15;
    const int ty = t >> 4;
    const int qt = blockIdx.x;
    const int bh = blockIdx.y;
    const int b  = bh >> 4;
    const int h  = bh & 15;
    const int q0 = qt << 6;

    // ---- load Q tile (rotated) ----
    const float* qbase = qb + ((size_t)(b * SS + q0)) * DD + h * DK;
    #pragma unroll
    for (int c = 0; c < 4; c++) {
        int idx = c * 256 + t;
        int row = idx >> 4;
        int d4  = (idx & 15) << 2;
        float4 v = *(const float4*)(qbase + (size_t)row * DD + d4);
        Qs[row*64 + ((d4+0+row)&63)] = v.x;
        Qs[row*64 + ((d4+1+row)&63)] = v.y;
        Qs[row*64 + ((d4+2+row)&63)] = v.z;
        Qs[row*64 + ((d4+3+row)&63)] = v.w;
    }

    int ri[4], rj[4];
    #pragma unroll
    for (int i = 0; i < 4; i++) ri[i] = ty + 16*i;
    #pragma unroll
    for (int j = 0; j < 4; j++) rj[j] = tx + 16*j;

    float o[4][4];
    float m_[4], l_[4];
    #pragma unroll
    for (int i = 0; i < 4; i++) {
        m_[i] = -1e30f; l_[i] = 0.0f;
        #pragma unroll
        for (int j = 0; j < 4; j++) o[i][j] = 0.0f;
    }

    for (int kt = 0; kt <= qt; kt++) {
        __syncthreads();  // previous iteration's P/V reads complete

        // ---- load K (rotated) and V (plain) tiles ----
        const float* kbase = kb + ((size_t)(b * SS + (kt << 6))) * DD + h * DK;
        const float* vbase = vb + ((size_t)(b * SS + (kt << 6))) * DD + h * DK;
        #pragma unroll
        for (int c = 0; c < 4; c++) {
            int idx = c * 256 + t;
            int row = idx >> 4;
            int d4  = (idx & 15) << 2;
            float4 kv = *(const float4*)(kbase + (size_t)row * DD + d4);
            KsPs[row*64 + ((d4+0+row)&63)] = kv.x;
            KsPs[row*64 + ((d4+1+row)&63)] = kv.y;
            KsPs[row*64 + ((d4+2+row)&63)] = kv.z;
            KsPs[row*64 + ((d4+3+row)&63)] = kv.w;
            float4 vv = *(const float4*)(vbase + (size_t)row * DD + d4);
            *(float4*)&Vs[row*64 + d4] = vv;
        }
        __syncthreads();

        // ---- scores S = Q K^T ----
        float s[4][4];
        #pragma unroll
        for (int i = 0; i < 4; i++)
            #pragma unroll
            for (int j = 0; j < 4; j++) s[i][j] = 0.0f;

        #pragma unroll 8
        for (int d = 0; d < 64; d++) {
            float qf[4], kf[4];
            #pragma unroll
            for (int i = 0; i < 4; i++) qf[i] = Qs[ri[i]*64 + ((d + ri[i]) & 63)];
            #pragma unroll
            for (int j = 0; j < 4; j++) kf[j] = KsPs[rj[j]*64 + ((d + rj[j]) & 63)];
            #pragma unroll
            for (int i = 0; i < 4; i++)
                #pragma unroll
                for (int j = 0; j < 4; j++)
                    s[i][j] += qf[i] * kf[j];
        }

        // ---- scale + causal mask (diagonal tile only) ----
        #pragma unroll
        for (int i = 0; i < 4; i++)
            #pragma unroll
            for (int j = 0; j < 4; j++) {
                float sv = s[i][j] * 0.125f;
                if (kt == qt && rj[j] > ri[i]) sv = -1e9f;
                s[i][j] = sv;
            }

        // ---- online softmax ----
        #pragma unroll
        for (int i = 0; i < 4; i++) {
            float rm = fmaxf(fmaxf(s[i][0], s[i][1]), fmaxf(s[i][2], s[i][3]));
            rm = fmaxf(rm, __shfl_xor_sync(0xffffffffu, rm, 1));
            rm = fmaxf(rm, __shfl_xor_sync(0xffffffffu, rm, 2));
            rm = fmaxf(rm, __shfl_xor_sync(0xffffffffu, rm, 4));
            rm = fmaxf(rm, __shfl_xor_sync(0xffffffffu, rm, 8));
            float mn = fmaxf(m_[i], rm);
            float alpha = __expf(m_[i] - mn);
            float rs = 0.0f;
            #pragma unroll
            for (int j = 0; j < 4; j++) {
                float p = __expf(s[i][j] - mn);
                s[i][j] = p;
                rs += p;
            }
            rs += __shfl_xor_sync(0xffffffffu, rs, 1);
            rs += __shfl_xor_sync(0xffffffffu, rs, 2);
            rs += __shfl_xor_sync(0xffffffffu, rs, 4);
            rs += __shfl_xor_sync(0xffffffffu, rs, 8);
            l_[i] = l_[i] * alpha + rs;
            m_[i] = mn;
            #pragma unroll
            for (int j = 0; j < 4; j++) o[i][j] *= alpha;
        }

        __syncthreads();  // all K reads done before overwriting with P

        // ---- write P into KsPs (rotated) ----
        #pragma unroll
        for (int i = 0; i < 4; i++)
            #pragma unroll
            for (int j = 0; j < 4; j++)
                KsPs[ri[i]*64 + ((rj[j] + ri[i]) & 63)] = s[i][j];
        __syncthreads();

        // ---- O += P V ----
        #pragma unroll 8
        for (int kk = 0; kk < 64; kk++) {
            float pf[4], vf[4];
            #pragma unroll
            for (int i = 0; i < 4; i++) pf[i] = KsPs[ri[i]*64 + ((kk + ri[i]) & 63)];
            #pragma unroll
            for (int j = 0; j < 4; j++) vf[j] = Vs[kk*64 + rj[j]];
            #pragma unroll
            for (int i = 0; i < 4; i++)
                #pragma unroll
                for (int j = 0; j < 4; j++)
                    o[i][j] += pf[i] * vf[j];
        }
    }

    // ---- epilogue: normalize and store ----
    float* obase = ob + ((size_t)(b * SS + q0)) * DD + h * DK;
    #pragma unroll
    for (int i = 0; i < 4; i++) {
        float inv = 1.0f / l_[i];
        #pragma unroll
        for (int j = 0; j < 4; j++)
            obase[(size_t)ri[i] * DD + rj[j]] = o[i][j] * inv;
    }
}

// ---------------- launch -----------------------------------------------------
extern "C" void kernel_launch(void* const* d_in, const int* in_sizes, int n_in,
                              void* d_out, int out_size)
{
    const float* Q  = (const float*)d_in[0];
    const float* K  = (const float*)d_in[1];
    const float* V  = (const float*)d_in[2];
    // d_in[3] = mask (causal by construction; handled analytically)
    const float* Wq = (const float*)d_in[4];
    const float* bq = (const float*)d_in[5];
    const float* Wk = (const float*)d_in[6];
    const float* bk = (const float*)d_in[7];
    const float* Wv = (const float*)d_in[8];
    const float* bv = (const float*)d_in[9];
    const float* Wo = (const float*)d_in[10];
    const float* bo = (const float*)d_in[11];

    float *gq, *gk, *gv, *ga;
    cudaGetSymbolAddress((void**)&gq, g_q);
    cudaGetSymbolAddress((void**)&gk, g_k);
    cudaGetSymbolAddress((void**)&gv, g_v);
    cudaGetSymbolAddress((void**)&ga, g_attn);

    dim3 gemmGrid(1024 / 128, MR / 128);   // (8, 32)
    gemm_nt_bias<<<gemmGrid, 256>>>(Q, Wq, bq, gq);
    gemm_nt_bias<<<gemmGrid, 256>>>(K, Wk, bk, gk);
    gemm_nt_bias<<<gemmGrid, 256>>>(V, Wv, bv, gv);

    dim3 attnGrid(SS / 64, BB * HH);       // (32, 32)
    flash_attn<<<attnGrid, 256>>>(gq, gk, gv, ga);

    gemm_nt_bias<<<gemmGrid, 256>>>(ga, Wo, bo, (float*)d_out);
}

// round 3
// speedup vs baseline: 1.4526x; 1.4526x over previous
#include <cuda_runtime.h>
#include <cuda_bf16.h>
#include <cstdint>

#define BB 2
#define SS 2048
#define DD 1024
#define HH 16
#define DK 64
#define MR (BB*SS)   // 4096 rows

// ---------------- scratch (device globals; no allocation allowed) ------------
__device__ float g_q[(size_t)MR * DD];
__device__ float g_k[(size_t)MR * DD];
__device__ float g_v[(size_t)MR * DD];
__device__ float g_attn[(size_t)MR * DD];
// bf16 hi/lo staging (reused across the 4 GEMMs — launches are sequential)
__device__ __align__(16) __nv_bfloat16 g_act_hi[(size_t)MR * DD];
__device__ __align__(16) __nv_bfloat16 g_act_lo[(size_t)MR * DD];
__device__ __align__(16) __nv_bfloat16 g_w_hi[(size_t)DD * DD];
__device__ __align__(16) __nv_bfloat16 g_w_lo[(size_t)DD * DD];

// ====================== helpers ==============================================
__device__ __forceinline__ uint32_t smem_u32(const void* p) {
    uint32_t a;
    asm("{ .reg .u64 t; cvta.to.shared.u64 t, %1; cvt.u32.u64 %0, t; }" : "=r"(a) : "l"(p));
    return a;
}
#define CP_ASYNC16(dst, src) \
    asm volatile("cp.async.cg.shared.global [%0], [%1], 16;" :: "r"(dst), "l"(src) : "memory")
#define CP_COMMIT() asm volatile("cp.async.commit_group;" ::: "memory")
#define CP_WAIT1()  asm volatile("cp.async.wait_group 1;" ::: "memory")
#define CP_WAIT0()  asm volatile("cp.async.wait_group 0;" ::: "memory")

#define LDSM_X4(r0,r1,r2,r3, addr) \
    asm volatile("ldmatrix.sync.aligned.m8n8.x4.shared.b16 {%0,%1,%2,%3}, [%4];" \
        : "=r"(r0), "=r"(r1), "=r"(r2), "=r"(r3) : "r"(addr))
#define LDSM_X2(r0,r1, addr) \
    asm volatile("ldmatrix.sync.aligned.m8n8.x2.shared.b16 {%0,%1}, [%2];" \
        : "=r"(r0), "=r"(r1) : "r"(addr))
#define MMA_BF16(d, a, b) \
    asm volatile("mma.sync.aligned.m16n8k16.row.col.f32.bf16.bf16.f32 " \
        "{%0,%1,%2,%3}, {%4,%5,%6,%7}, {%8,%9}, {%0,%1,%2,%3};" \
        : "+f"((d)[0]), "+f"((d)[1]), "+f"((d)[2]), "+f"((d)[3]) \
        : "r"((a)[0]), "r"((a)[1]), "r"((a)[2]), "r"((a)[3]), \
          "r"((b)[0]), "r"((b)[1]))

// ====================== fp32 -> bf16 hi/lo split =============================
__global__ __launch_bounds__(256) void split_f32(
    const float* __restrict__ in, __nv_bfloat16* __restrict__ hi,
    __nv_bfloat16* __restrict__ lo, int n4)
{
    int i = blockIdx.x * 256 + threadIdx.x;
    if (i >= n4) return;
    float4 x = ((const float4*)in)[i];
    __nv_bfloat16 h0 = __float2bfloat16(x.x), h1 = __float2bfloat16(x.y);
    __nv_bfloat16 h2 = __float2bfloat16(x.z), h3 = __float2bfloat16(x.w);
    __nv_bfloat16 l0 = __float2bfloat16(x.x - __bfloat162float(h0));
    __nv_bfloat16 l1 = __float2bfloat16(x.y - __bfloat162float(h1));
    __nv_bfloat16 l2 = __float2bfloat16(x.z - __bfloat162float(h2));
    __nv_bfloat16 l3 = __float2bfloat16(x.w - __bfloat162float(h3));
    __nv_bfloat162* hp = (__nv_bfloat162*)hi;
    __nv_bfloat162* lp = (__nv_bfloat162*)lo;
    hp[2*i]   = __nv_bfloat162(h0, h1);
    hp[2*i+1] = __nv_bfloat162(h2, h3);
    lp[2*i]   = __nv_bfloat162(l0, l1);
    lp[2*i+1] = __nv_bfloat162(l2, l3);
}

// ====================== mma.sync GEMM: C = A*W^T + bias ======================
// 128x128 tile/CTA, BK=32, split-bf16 3-pass (AhiBhi + AhiBlo + AloBhi),
// cp.async double-buffered SMEM, 8 warps (2m x 4n), 64x32 warp tile.
// SMEM tile row stride 80B -> conflict-free ldmatrix.
#define TSTRIDE 80
#define TILE_B  (128 * TSTRIDE)          // 10240 B per operand tile
#define BUF_B   (4 * TILE_B)             // Ahi, Alo, Bhi, Blo
#define GEMM_SMEM (2 * BUF_B)            // 81920 B

__global__ __launch_bounds__(256, 2) void gemm_mma(
    const __nv_bfloat16* __restrict__ Ahi, const __nv_bfloat16* __restrict__ Alo,
    const __nv_bfloat16* __restrict__ Bhi, const __nv_bfloat16* __restrict__ Blo,
    const float* __restrict__ bias, float* __restrict__ C)
{
    extern __shared__ char smem[];
    const uint32_t sbase = smem_u32(smem);
    const int t    = threadIdx.x;
    const int lane = t & 31;
    const int wid  = t >> 5;
    const int wm   = wid & 1;       // 2 warps along M (64 rows each)
    const int wn   = wid >> 1;      // 4 warps along N (32 cols each)
    const int rowBase = blockIdx.y << 7;
    const int colBase = blockIdx.x << 7;

    const __nv_bfloat16* srcs[4] = {
        Ahi + (size_t)rowBase * DD, Alo + (size_t)rowBase * DD,
        Bhi + (size_t)colBase * DD, Blo + (size_t)colBase * DD };

    // per-thread load coords: 2 iters x 4 tiles; idx -> (row, 16B-seg)
    const int r0 = t >> 2;          // rows 0..63   (iter 0)
    const int r1 = 64 + (t >> 2);   // rows 64..127 (iter 1)
    const int sg = t & 3;           // 16B segment 0..3

    float acc[4][4][4];
    #pragma unroll
    for (int i = 0; i < 4; i++)
        #pragma unroll
        for (int j = 0; j < 4; j++)
            #pragma unroll
            for (int e = 0; e < 4; e++) acc[i][j][e] = 0.0f;

    // ---- prologue: load chunk 0 into buf 0 ----
    {
        const uint32_t base = sbase;
        #pragma unroll
        for (int tile = 0; tile < 4; tile++) {
            const __nv_bfloat16* s = srcs[tile] + sg * 8;
            uint32_t d = base + tile * TILE_B + sg * 16;
            CP_ASYNC16(d + r0 * TSTRIDE, s + (size_t)r0 * DD);
            CP_ASYNC16(d + r1 * TSTRIDE, s + (size_t)r1 * DD);
        }
        CP_COMMIT();
    }

    for (int c = 0; c < 32; c++) {
        // prefetch next chunk into other buffer
        if (c + 1 < 32) {
            const uint32_t base = sbase + ((c + 1) & 1) * BUF_B;
            const int k0 = (c + 1) * 32;
            #pragma unroll
            for (int tile = 0; tile < 4; tile++) {
                const __nv_bfloat16* s = srcs[tile] + k0 + sg * 8;
                uint32_t d = base + tile * TILE_B + sg * 16;
                CP_ASYNC16(d + r0 * TSTRIDE, s + (size_t)r0 * DD);
                CP_ASYNC16(d + r1 * TSTRIDE, s + (size_t)r1 * DD);
            }
            CP_COMMIT();
            CP_WAIT1();     // current chunk's group complete
        } else {
            CP_WAIT0();
        }
        __syncthreads();

        const uint32_t base = sbase + (c & 1) * BUF_B;
        // 3 passes: (Ahi,Bhi), (Ahi,Blo), (Alo,Bhi)
        #pragma unroll
        for (int p = 0; p < 3; p++) {
            const uint32_t aT = base + (p == 2 ? TILE_B : 0);
            const uint32_t bT = base + 2 * TILE_B + (p == 1 ? TILE_B : 0);
            #pragma unroll
            for (int ks = 0; ks < 2; ks++) {
                uint32_t a[4][4];
                #pragma unroll
                for (int mt = 0; mt < 4; mt++) {
                    uint32_t addr = aT
                        + (wm * 64 + mt * 16 + (lane & 15)) * TSTRIDE
                        + (ks * 16 + (lane >> 4) * 8) * 2;
                    LDSM_X4(a[mt][0], a[mt][1], a[mt][2], a[mt][3], addr);
                }
                uint32_t b[4][2];
                const int l = lane & 15;
                #pragma unroll
                for (int nt = 0; nt < 4; nt++) {
                    uint32_t addr = bT
                        + (wn * 32 + nt * 8 + (l & 7)) * TSTRIDE
                        + (ks * 16 + ((l >> 3) & 1) * 8) * 2;
                    LDSM_X2(b[nt][0], b[nt][1], addr);
                }
                #pragma unroll
                for (int mt = 0; mt < 4; mt++)
                    #pragma unroll
                    for (int nt = 0; nt < 4; nt++)
                        MMA_BF16(acc[mt][nt], a[mt], b[nt]);
            }
        }
        __syncthreads();
    }

    // ---- epilogue: acc -> C with bias ----
    const int g   = lane >> 2;
    const int tig = lane & 3;
    #pragma unroll
    for (int mt = 0; mt < 4; mt++) {
        const int row = rowBase + wm * 64 + mt * 16 + g;
        #pragma unroll
        for (int nt = 0; nt < 4; nt++) {
            const int col = colBase + wn * 32 + nt * 8 + 2 * tig;
            float2 bv = *(const float2*)(bias + col);
            float2 o0, o1;
            o0.x = acc[mt][nt][0] + bv.x;  o0.y = acc[mt][nt][1] + bv.y;
            o1.x = acc[mt][nt][2] + bv.x;  o1.y = acc[mt][nt][3] + bv.y;
            *(float2*)(C + (size_t)row * DD + col)       = o0;
            *(float2*)(C + (size_t)(row + 8) * DD + col) = o1;
        }
    }
}

// ---------------- Flash attention (causal), fp32 SIMT (unchanged) ------------
__global__ __launch_bounds__(256) void flash_attn(
    const float* __restrict__ qb, const float* __restrict__ kb,
    const float* __restrict__ vb, float* __restrict__ ob)
{
    __shared__ float Qs[64 * 64];
    __shared__ float KsPs[64 * 64];
    __shared__ float Vs[64 * 64];

    const int t  = threadIdx.x;
    const int tx = t & 15;
    const int ty = t >> 4;
    const int qt = blockIdx.x;
    const int bh = blockIdx.y;
    const int b  = bh >> 4;
    const int h  = bh & 15;
    const int q0 = qt << 6;

    const float* qbase = qb + ((size_t)(b * SS + q0)) * DD + h * DK;
    #pragma unroll
    for (int c = 0; c < 4; c++) {
        int idx = c * 256 + t;
        int row = idx >> 4;
        int d4  = (idx & 15) << 2;
        float4 v = *(const float4*)(qbase + (size_t)row * DD + d4);
        Qs[row*64 + ((d4+0+row)&63)] = v.x;
        Qs[row*64 + ((d4+1+row)&63)] = v.y;
        Qs[row*64 + ((d4+2+row)&63)] = v.z;
        Qs[row*64 + ((d4+3+row)&63)] = v.w;
    }

    int ri[4], rj[4];
    #pragma unroll
    for (int i = 0; i < 4; i++) ri[i] = ty + 16*i;
    #pragma unroll
    for (int j = 0; j < 4; j++) rj[j] = tx + 16*j;

    float o[4][4];
    float m_[4], l_[4];
    #pragma unroll
    for (int i = 0; i < 4; i++) {
        m_[i] = -1e30f; l_[i] = 0.0f;
        #pragma unroll
        for (int j = 0; j < 4; j++) o[i][j] = 0.0f;
    }

    for (int kt = 0; kt <= qt; kt++) {
        __syncthreads();

        const float* kbase = kb + ((size_t)(b * SS + (kt << 6))) * DD + h * DK;
        const float* vbase = vb + ((size_t)(b * SS + (kt << 6))) * DD + h * DK;
        #pragma unroll
        for (int c = 0; c < 4; c++) {
            int idx = c * 256 + t;
            int row = idx >> 4;
            int d4  = (idx & 15) << 2;
            float4 kv = *(const float4*)(kbase + (size_t)row * DD + d4);
            KsPs[row*64 + ((d4+0+row)&63)] = kv.x;
            KsPs[row*64 + ((d4+1+row)&63)] = kv.y;
            KsPs[row*64 + ((d4+2+row)&63)] = kv.z;
            KsPs[row*64 + ((d4+3+row)&63)] = kv.w;
            float4 vv = *(const float4*)(vbase + (size_t)row * DD + d4);
            *(float4*)&Vs[row*64 + d4] = vv;
        }
        __syncthreads();

        float s[4][4];
        #pragma unroll
        for (int i = 0; i < 4; i++)
            #pragma unroll
            for (int j = 0; j < 4; j++) s[i][j] = 0.0f;

        #pragma unroll 8
        for (int d = 0; d < 64; d++) {
            float qf[4], kf[4];
            #pragma unroll
            for (int i = 0; i < 4; i++) qf[i] = Qs[ri[i]*64 + ((d + ri[i]) & 63)];
            #pragma unroll
            for (int j = 0; j < 4; j++) kf[j] = KsPs[rj[j]*64 + ((d + rj[j]) & 63)];
            #pragma unroll
            for (int i = 0; i < 4; i++)
                #pragma unroll
                for (int j = 0; j < 4; j++)
                    s[i][j] += qf[i] * kf[j];
        }

        #pragma unroll
        for (int i = 0; i < 4; i++)
            #pragma unroll
            for (int j = 0; j < 4; j++) {
                float sv = s[i][j] * 0.125f;
                if (kt == qt && rj[j] > ri[i]) sv = -1e9f;
                s[i][j] = sv;
            }

        #pragma unroll
        for (int i = 0; i < 4; i++) {
            float rm = fmaxf(fmaxf(s[i][0], s[i][1]), fmaxf(s[i][2], s[i][3]));
            rm = fmaxf(rm, __shfl_xor_sync(0xffffffffu, rm, 1));
            rm = fmaxf(rm, __shfl_xor_sync(0xffffffffu, rm, 2));
            rm = fmaxf(rm, __shfl_xor_sync(0xffffffffu, rm, 4));
            rm = fmaxf(rm, __shfl_xor_sync(0xffffffffu, rm, 8));
            float mn = fmaxf(m_[i], rm);
            float alpha = __expf(m_[i] - mn);
            float rs = 0.0f;
            #pragma unroll
            for (int j = 0; j < 4; j++) {
                float p = __expf(s[i][j] - mn);
                s[i][j] = p;
                rs += p;
            }
            rs += __shfl_xor_sync(0xffffffffu, rs, 1);
            rs += __shfl_xor_sync(0xffffffffu, rs, 2);
            rs += __shfl_xor_sync(0xffffffffu, rs, 4);
            rs += __shfl_xor_sync(0xffffffffu, rs, 8);
            l_[i] = l_[i] * alpha + rs;
            m_[i] = mn;
            #pragma unroll
            for (int j = 0; j < 4; j++) o[i][j] *= alpha;
        }

        __syncthreads();

        #pragma unroll
        for (int i = 0; i < 4; i++)
            #pragma unroll
            for (int j = 0; j < 4; j++)
                KsPs[ri[i]*64 + ((rj[j] + ri[i]) & 63)] = s[i][j];
        __syncthreads();

        #pragma unroll 8
        for (int kk = 0; kk < 64; kk++) {
            float pf[4], vf[4];
            #pragma unroll
            for (int i = 0; i < 4; i++) pf[i] = KsPs[ri[i]*64 + ((kk + ri[i]) & 63)];
            #pragma unroll
            for (int j = 0; j < 4; j++) vf[j] = Vs[kk*64 + rj[j]];
            #pragma unroll
            for (int i = 0; i < 4; i++)
                #pragma unroll
                for (int j = 0; j < 4; j++)
                    o[i][j] += pf[i] * vf[j];
        }
    }

    float* obase = ob + ((size_t)(b * SS + q0)) * DD + h * DK;
    #pragma unroll
    for (int i = 0; i < 4; i++) {
        float inv = 1.0f / l_[i];
        #pragma unroll
        for (int j = 0; j < 4; j++)
            obase[(size_t)ri[i] * DD + rj[j]] = o[i][j] * inv;
    }
}

// ---------------- launch -----------------------------------------------------
extern "C" void kernel_launch(void* const* d_in, const int* in_sizes, int n_in,
                              void* d_out, int out_size)
{
    const float* Q  = (const float*)d_in[0];
    const float* K  = (const float*)d_in[1];
    const float* V  = (const float*)d_in[2];
    // d_in[3] = mask (causal by construction; handled analytically)
    const float* Wq = (const float*)d_in[4];
    const float* bq = (const float*)d_in[5];
    const float* Wk = (const float*)d_in[6];
    const float* bk = (const float*)d_in[7];
    const float* Wv = (const float*)d_in[8];
    const float* bv = (const float*)d_in[9];
    const float* Wo = (const float*)d_in[10];
    const float* bo = (const float*)d_in[11];

    float *gq, *gk, *gv, *ga;
    __nv_bfloat16 *ahi, *alo, *whi, *wlo;
    cudaGetSymbolAddress((void**)&gq, g_q);
    cudaGetSymbolAddress((void**)&gk, g_k);
    cudaGetSymbolAddress((void**)&gv, g_v);
    cudaGetSymbolAddress((void**)&ga, g_attn);
    cudaGetSymbolAddress((void**)&ahi, g_act_hi);
    cudaGetSymbolAddress((void**)&alo, g_act_lo);
    cudaGetSymbolAddress((void**)&whi, g_w_hi);
    cudaGetSymbolAddress((void**)&wlo, g_w_lo);

    cudaFuncSetAttribute(gemm_mma, cudaFuncAttributeMaxDynamicSharedMemorySize, GEMM_SMEM);

    const int nAct4 = MR * DD / 4;   // 1,048,576
    const int nW4   = DD * DD / 4;   // 262,144
    dim3 gemmGrid(DD / 128, MR / 128);   // (8, 32)

    // Q projection
    split_f32<<<(nAct4 + 255) / 256, 256>>>(Q, ahi, alo, nAct4);
    split_f32<<<(nW4 + 255) / 256, 256>>>(Wq, whi, wlo, nW4);
    gemm_mma<<<gemmGrid, 256, GEMM_SMEM>>>(ahi, alo, whi, wlo, bq, gq);
    // K projection
    split_f32<<<(nAct4 + 255) / 256, 256>>>(K, ahi, alo, nAct4);
    split_f32<<<(nW4 + 255) / 256, 256>>>(Wk, whi, wlo, nW4);
    gemm_mma<<<gemmGrid, 256, GEMM_SMEM>>>(ahi, alo, whi, wlo, bk, gk);
    // V projection
    split_f32<<<(nAct4 + 255) / 256, 256>>>(V, ahi, alo, nAct4);
    split_f32<<<(nW4 + 255) / 256, 256>>>(Wv, whi, wlo, nW4);
    gemm_mma<<<gemmGrid, 256, GEMM_SMEM>>>(ahi, alo, whi, wlo, bv, gv);

    // attention
    dim3 attnGrid(SS / 64, BB * HH);       // (32, 32)
    flash_attn<<<attnGrid, 256>>>(gq, gk, gv, ga);

    // output projection
    split_f32<<<(nAct4 + 255) / 256, 256>>>(ga, ahi, alo, nAct4);
    split_f32<<<(nW4 + 255) / 256, 256>>>(Wo, whi, wlo, nW4);
    gemm_mma<<<gemmGrid, 256, GEMM_SMEM>>>(ahi, alo, whi, wlo, bo, (float*)d_out);
}

// round 4
// speedup vs baseline: 3.9333x; 2.7077x over previous
#include <cuda_runtime.h>
#include <cuda_bf16.h>
#include <cstdint>

#define BB 2
#define SS 2048
#define DD 1024
#define HH 16
#define DK 64
#define MR (BB*SS)   // 4096 rows

// ---------------- scratch (device globals; no allocation allowed) ------------
__device__ float g_attn[(size_t)MR * DD];
__device__ __align__(16) __nv_bfloat16 g_qh[(size_t)MR * DD];
__device__ __align__(16) __nv_bfloat16 g_ql[(size_t)MR * DD];
__device__ __align__(16) __nv_bfloat16 g_kh[(size_t)MR * DD];
__device__ __align__(16) __nv_bfloat16 g_kl[(size_t)MR * DD];
__device__ __align__(16) __nv_bfloat16 g_vh[(size_t)MR * DD];
__device__ __align__(16) __nv_bfloat16 g_vl[(size_t)MR * DD];
__device__ __align__(16) __nv_bfloat16 g_act_hi[(size_t)MR * DD];
__device__ __align__(16) __nv_bfloat16 g_act_lo[(size_t)MR * DD];
__device__ __align__(16) __nv_bfloat16 g_w_hi[(size_t)DD * DD];
__device__ __align__(16) __nv_bfloat16 g_w_lo[(size_t)DD * DD];

// ====================== helpers ==============================================
__device__ __forceinline__ uint32_t smem_u32(const void* p) {
    uint32_t a;
    asm("{ .reg .u64 t; cvta.to.shared.u64 t, %1; cvt.u32.u64 %0, t; }" : "=r"(a) : "l"(p));
    return a;
}
#define CP_ASYNC16(dst, src) \
    asm volatile("cp.async.cg.shared.global [%0], [%1], 16;" :: "r"(dst), "l"(src) : "memory")
#define CP_COMMIT() asm volatile("cp.async.commit_group;" ::: "memory")
#define CP_WAIT1()  asm volatile("cp.async.wait_group 1;" ::: "memory")
#define CP_WAIT0()  asm volatile("cp.async.wait_group 0;" ::: "memory")

#define LDSM_X4(r0,r1,r2,r3, addr) \
    asm volatile("ldmatrix.sync.aligned.m8n8.x4.shared.b16 {%0,%1,%2,%3}, [%4];" \
        : "=r"(r0), "=r"(r1), "=r"(r2), "=r"(r3) : "r"(addr))
#define LDSM_X2(r0,r1, addr) \
    asm volatile("ldmatrix.sync.aligned.m8n8.x2.shared.b16 {%0,%1}, [%2];" \
        : "=r"(r0), "=r"(r1) : "r"(addr))
#define LDSM_X2T(r0,r1, addr) \
    asm volatile("ldmatrix.sync.aligned.m8n8.x2.trans.shared.b16 {%0,%1}, [%2];" \
        : "=r"(r0), "=r"(r1) : "r"(addr))
#define MMA_BF16(d, a, b) \
    asm volatile("mma.sync.aligned.m16n8k16.row.col.f32.bf16.bf16.f32 " \
        "{%0,%1,%2,%3}, {%4,%5,%6,%7}, {%8,%9}, {%0,%1,%2,%3};" \
        : "+f"((d)[0]), "+f"((d)[1]), "+f"((d)[2]), "+f"((d)[3]) \
        : "r"((a)[0]), "r"((a)[1]), "r"((a)[2]), "r"((a)[3]), \
          "r"((b)[0]), "r"((b)[1]))
#define MMA_BF16_2(d, a, b0, b1) \
    asm volatile("mma.sync.aligned.m16n8k16.row.col.f32.bf16.bf16.f32 " \
        "{%0,%1,%2,%3}, {%4,%5,%6,%7}, {%8,%9}, {%0,%1,%2,%3};" \
        : "+f"((d)[0]), "+f"((d)[1]), "+f"((d)[2]), "+f"((d)[3]) \
        : "r"((a)[0]), "r"((a)[1]), "r"((a)[2]), "r"((a)[3]), \
          "r"(b0), "r"(b1))

// ====================== fp32 -> bf16 hi/lo split =============================
__global__ __launch_bounds__(256) void split_f32(
    const float* __restrict__ in, __nv_bfloat16* __restrict__ hi,
    __nv_bfloat16* __restrict__ lo, int n4)
{
    int i = blockIdx.x * 256 + threadIdx.x;
    if (i >= n4) return;
    float4 x = ((const float4*)in)[i];
    __nv_bfloat16 h0 = __float2bfloat16(x.x), h1 = __float2bfloat16(x.y);
    __nv_bfloat16 h2 = __float2bfloat16(x.z), h3 = __float2bfloat16(x.w);
    __nv_bfloat16 l0 = __float2bfloat16(x.x - __bfloat162float(h0));
    __nv_bfloat16 l1 = __float2bfloat16(x.y - __bfloat162float(h1));
    __nv_bfloat16 l2 = __float2bfloat16(x.z - __bfloat162float(h2));
    __nv_bfloat16 l3 = __float2bfloat16(x.w - __bfloat162float(h3));
    __nv_bfloat162* hp = (__nv_bfloat162*)hi;
    __nv_bfloat162* lp = (__nv_bfloat162*)lo;
    hp[2*i]   = __nv_bfloat162(h0, h1);
    hp[2*i+1] = __nv_bfloat162(h2, h3);
    lp[2*i]   = __nv_bfloat162(l0, l1);
    lp[2*i+1] = __nv_bfloat162(l2, l3);
}

// ====================== mma.sync GEMM: C = A*W^T + bias ======================
// 128x128 tile/CTA, BK=32, split-bf16 3-pass, cp.async double-buffered SMEM.
// Epilogue: fp32 out (Cf32) OR scaled bf16 hi/lo out (Chi/Clo).
#define TSTRIDE 80
#define TILE_B  (128 * TSTRIDE)
#define BUF_B   (4 * TILE_B)
#define GEMM_SMEM (2 * BUF_B)            // 81920 B

__global__ __launch_bounds__(256, 2) void gemm_mma(
    const __nv_bfloat16* __restrict__ Ahi, const __nv_bfloat16* __restrict__ Alo,
    const __nv_bfloat16* __restrict__ Bhi, const __nv_bfloat16* __restrict__ Blo,
    const float* __restrict__ bias, float* __restrict__ Cf32,
    __nv_bfloat16* __restrict__ Chi, __nv_bfloat16* __restrict__ Clo,
    float scale)
{
    extern __shared__ char smem[];
    const uint32_t sbase = smem_u32(smem);
    const int t    = threadIdx.x;
    const int lane = t & 31;
    const int wid  = t >> 5;
    const int wm   = wid & 1;
    const int wn   = wid >> 1;
    const int rowBase = blockIdx.y << 7;
    const int colBase = blockIdx.x << 7;

    const __nv_bfloat16* srcs[4] = {
        Ahi + (size_t)rowBase * DD, Alo + (size_t)rowBase * DD,
        Bhi + (size_t)colBase * DD, Blo + (size_t)colBase * DD };

    const int r0 = t >> 2;
    const int r1 = 64 + (t >> 2);
    const int sg = t & 3;

    float acc[4][4][4];
    #pragma unroll
    for (int i = 0; i < 4; i++)
        #pragma unroll
        for (int j = 0; j < 4; j++)
            #pragma unroll
            for (int e = 0; e < 4; e++) acc[i][j][e] = 0.0f;

    {
        const uint32_t base = sbase;
        #pragma unroll
        for (int tile = 0; tile < 4; tile++) {
            const __nv_bfloat16* s = srcs[tile] + sg * 8;
            uint32_t d = base + tile * TILE_B + sg * 16;
            CP_ASYNC16(d + r0 * TSTRIDE, s + (size_t)r0 * DD);
            CP_ASYNC16(d + r1 * TSTRIDE, s + (size_t)r1 * DD);
        }
        CP_COMMIT();
    }

    for (int c = 0; c < 32; c++) {
        if (c + 1 < 32) {
            const uint32_t base = sbase + ((c + 1) & 1) * BUF_B;
            const int k0 = (c + 1) * 32;
            #pragma unroll
            for (int tile = 0; tile < 4; tile++) {
                const __nv_bfloat16* s = srcs[tile] + k0 + sg * 8;
                uint32_t d = base + tile * TILE_B + sg * 16;
                CP_ASYNC16(d + r0 * TSTRIDE, s + (size_t)r0 * DD);
                CP_ASYNC16(d + r1 * TSTRIDE, s + (size_t)r1 * DD);
            }
            CP_COMMIT();
            CP_WAIT1();
        } else {
            CP_WAIT0();
        }
        __syncthreads();

        const uint32_t base = sbase + (c & 1) * BUF_B;
        #pragma unroll
        for (int p = 0; p < 3; p++) {
            const uint32_t aT = base + (p == 2 ? TILE_B : 0);
            const uint32_t bT = base + 2 * TILE_B + (p == 1 ? TILE_B : 0);
            #pragma unroll
            for (int ks = 0; ks < 2; ks++) {
                uint32_t a[4][4];
                #pragma unroll
                for (int mt = 0; mt < 4; mt++) {
                    uint32_t addr = aT
                        + (wm * 64 + mt * 16 + (lane & 15)) * TSTRIDE
                        + (ks * 16 + (lane >> 4) * 8) * 2;
                    LDSM_X4(a[mt][0], a[mt][1], a[mt][2], a[mt][3], addr);
                }
                uint32_t b[4][2];
                const int l = lane & 15;
                #pragma unroll
                for (int nt = 0; nt < 4; nt++) {
                    uint32_t addr = bT
                        + (wn * 32 + nt * 8 + (l & 7)) * TSTRIDE
                        + (ks * 16 + ((l >> 3) & 1) * 8) * 2;
                    LDSM_X2(b[nt][0], b[nt][1], addr);
                }
                #pragma unroll
                for (int mt = 0; mt < 4; mt++)
                    #pragma unroll
                    for (int nt = 0; nt < 4; nt++)
                        MMA_BF16(acc[mt][nt], a[mt], b[nt]);
            }
        }
        __syncthreads();
    }

    const int g   = lane >> 2;
    const int tig = lane & 3;
    #pragma unroll
    for (int mt = 0; mt < 4; mt++) {
        const int row = rowBase + wm * 64 + mt * 16 + g;
        #pragma unroll
        for (int nt = 0; nt < 4; nt++) {
            const int col = colBase + wn * 32 + nt * 8 + 2 * tig;
            float2 bv = *(const float2*)(bias + col);
            float c00 = (acc[mt][nt][0] + bv.x) * scale;
            float c01 = (acc[mt][nt][1] + bv.y) * scale;
            float c10 = (acc[mt][nt][2] + bv.x) * scale;
            float c11 = (acc[mt][nt][3] + bv.y) * scale;
            if (Cf32) {
                *(float2*)(Cf32 + (size_t)row * DD + col)       = make_float2(c00, c01);
                *(float2*)(Cf32 + (size_t)(row + 8) * DD + col) = make_float2(c10, c11);
            } else {
                __nv_bfloat162 h0 = __floats2bfloat162_rn(c00, c01);
                __nv_bfloat162 h1 = __floats2bfloat162_rn(c10, c11);
                __nv_bfloat162 l0 = __floats2bfloat162_rn(
                    c00 - __bfloat162float(h0.x), c01 - __bfloat162float(h0.y));
                __nv_bfloat162 l1 = __floats2bfloat162_rn(
                    c10 - __bfloat162float(h1.x), c11 - __bfloat162float(h1.y));
                *(__nv_bfloat162*)(Chi + (size_t)row * DD + col)       = h0;
                *(__nv_bfloat162*)(Chi + (size_t)(row + 8) * DD + col) = h1;
                *(__nv_bfloat162*)(Clo + (size_t)row * DD + col)       = l0;
                *(__nv_bfloat162*)(Clo + (size_t)(row + 8) * DD + col) = l1;
            }
        }
    }
}

// ====================== Flash attention, mma.sync bf16 =======================
// grid=(S/64, B*H), 128 threads (4 warps, warp = 16 q-rows). BK=64, DK=64.
// SMEM tiles stride 144B. K/V hi/lo double-buffered via cp.async.
#define FSTR 144
#define FTILE (64 * FSTR)                 // 9216 B
#define FLASH_SMEM (2 * FTILE + 2 * 4 * FTILE)   // Qhi,Qlo + 2 bufs x {Khi,Klo,Vhi,Vlo}

__global__ __launch_bounds__(128) void flash_mma(
    const __nv_bfloat16* __restrict__ qhi, const __nv_bfloat16* __restrict__ qlo,
    const __nv_bfloat16* __restrict__ khi, const __nv_bfloat16* __restrict__ klo,
    const __nv_bfloat16* __restrict__ vhi, const __nv_bfloat16* __restrict__ vlo,
    float* __restrict__ ob)
{
    extern __shared__ char fsm[];
    const uint32_t sb = smem_u32(fsm);
    const int t = threadIdx.x, lane = t & 31, w = t >> 5;
    const int qt = blockIdx.x, bh = blockIdx.y, b = bh >> 4, h = bh & 15;
    const int q0 = qt << 6;

    const uint32_t Qh = sb, Ql = sb + FTILE;
    const uint32_t KV0 = sb + 2 * FTILE;

    const size_t hoff = (size_t)h * DK;
    const __nv_bfloat16* qsrc[2] = {
        qhi + (size_t)(b * SS + q0) * DD + hoff,
        qlo + (size_t)(b * SS + q0) * DD + hoff };

    // prologue: Q tiles + KV(kt=0)
    #pragma unroll
    for (int ti = 0; ti < 2; ti++)
        #pragma unroll
        for (int it = 0; it < 4; it++) {
            int idx = it * 128 + t, row = idx >> 3, sg = idx & 7;
            CP_ASYNC16((ti ? Ql : Qh) + row * FSTR + sg * 16,
                       qsrc[ti] + (size_t)row * DD + sg * 8);
        }
    {
        const size_t base0 = (size_t)(b * SS) * DD + hoff;
        const __nv_bfloat16* src[4] = { khi + base0, klo + base0, vhi + base0, vlo + base0 };
        #pragma unroll
        for (int ti = 0; ti < 4; ti++) {
            uint32_t dstT = KV0 + ti * FTILE;
            #pragma unroll
            for (int it = 0; it < 4; it++) {
                int idx = it * 128 + t, row = idx >> 3, sg = idx & 7;
                CP_ASYNC16(dstT + row * FSTR + sg * 16, src[ti] + (size_t)row * DD + sg * 8);
            }
        }
    }
    CP_COMMIT();

    float o[8][4];
    #pragma unroll
    for (int nb = 0; nb < 8; nb++)
        #pragma unroll
        for (int e = 0; e < 4; e++) o[nb][e] = 0.0f;
    float m0 = -1e30f, m1 = -1e30f, l0 = 0.0f, l1 = 0.0f;

    uint32_t qa_h[4][4], qa_l[4][4];

    const int row_loc0 = w * 16 + (lane >> 2);

    for (int kt = 0; kt <= qt; kt++) {
        if (kt > 0) __syncthreads();    // all warps done with buf (kt+1)&1's old data
        if (kt < qt) {
            const size_t base = (size_t)(b * SS + ((kt + 1) << 6)) * DD + hoff;
            const __nv_bfloat16* src[4] = { khi + base, klo + base, vhi + base, vlo + base };
            const uint32_t bufb = KV0 + ((kt + 1) & 1) * 4 * FTILE;
            #pragma unroll
            for (int ti = 0; ti < 4; ti++) {
                uint32_t dstT = bufb + ti * FTILE;
                #pragma unroll
                for (int it = 0; it < 4; it++) {
                    int idx = it * 128 + t, row = idx >> 3, sg = idx & 7;
                    CP_ASYNC16(dstT + row * FSTR + sg * 16, src[ti] + (size_t)row * DD + sg * 8);
                }
            }
            CP_COMMIT();
            CP_WAIT1();
        } else {
            CP_WAIT0();
        }
        __syncthreads();

        if (kt == 0) {
            #pragma unroll
            for (int ks = 0; ks < 4; ks++) {
                uint32_t addr = Qh + (w * 16 + (lane & 15)) * FSTR + ks * 32 + (lane >> 4) * 16;
                LDSM_X4(qa_h[ks][0], qa_h[ks][1], qa_h[ks][2], qa_h[ks][3], addr);
                addr = Ql + (w * 16 + (lane & 15)) * FSTR + ks * 32 + (lane >> 4) * 16;
                LDSM_X4(qa_l[ks][0], qa_l[ks][1], qa_l[ks][2], qa_l[ks][3], addr);
            }
        }

        const uint32_t Kh = KV0 + (kt & 1) * 4 * FTILE;
        const uint32_t Kl = Kh + FTILE;
        const uint32_t Vh = Kh + 2 * FTILE;
        const uint32_t Vl = Kh + 3 * FTILE;

        // ---- S = QK^T (3-pass split) ----
        float s[8][4];
        #pragma unroll
        for (int nb = 0; nb < 8; nb++)
            #pragma unroll
            for (int e = 0; e < 4; e++) s[nb][e] = 0.0f;

        #pragma unroll
        for (int ks = 0; ks < 4; ks++) {
            #pragma unroll
            for (int nb2 = 0; nb2 < 4; nb2++) {
                uint32_t off = (nb2 * 16 + ((lane >> 4) << 3) + (lane & 7)) * FSTR
                             + ks * 32 + ((lane >> 3) & 1) * 16;
                uint32_t bh_[4], bl_[4];
                LDSM_X4(bh_[0], bh_[1], bh_[2], bh_[3], Kh + off);
                LDSM_X4(bl_[0], bl_[1], bl_[2], bl_[3], Kl + off);
                MMA_BF16_2(s[2*nb2],   qa_h[ks], bh_[0], bh_[1]);
                MMA_BF16_2(s[2*nb2],   qa_l[ks], bh_[0], bh_[1]);
                MMA_BF16_2(s[2*nb2],   qa_h[ks], bl_[0], bl_[1]);
                MMA_BF16_2(s[2*nb2+1], qa_h[ks], bh_[2], bh_[3]);
                MMA_BF16_2(s[2*nb2+1], qa_l[ks], bh_[2], bh_[3]);
                MMA_BF16_2(s[2*nb2+1], qa_h[ks], bl_[2], bl_[3]);
            }
        }

        // ---- causal mask (diagonal tile) ----
        if (kt == qt) {
            #pragma unroll
            for (int nb = 0; nb < 8; nb++) {
                int c0 = nb * 8 + (lane & 3) * 2;
                if (c0     > row_loc0)     s[nb][0] = -1e30f;
                if (c0 + 1 > row_loc0)     s[nb][1] = -1e30f;
                if (c0     > row_loc0 + 8) s[nb][2] = -1e30f;
                if (c0 + 1 > row_loc0 + 8) s[nb][3] = -1e30f;
            }
        }

        // ---- online softmax ----
        float rm0 = -1e30f, rm1 = -1e30f;
        #pragma unroll
        for (int nb = 0; nb < 8; nb++) {
            rm0 = fmaxf(rm0, fmaxf(s[nb][0], s[nb][1]));
            rm1 = fmaxf(rm1, fmaxf(s[nb][2], s[nb][3]));
        }
        rm0 = fmaxf(rm0, __shfl_xor_sync(0xffffffffu, rm0, 1));
        rm0 = fmaxf(rm0, __shfl_xor_sync(0xffffffffu, rm0, 2));
        rm1 = fmaxf(rm1, __shfl_xor_sync(0xffffffffu, rm1, 1));
        rm1 = fmaxf(rm1, __shfl_xor_sync(0xffffffffu, rm1, 2));
        float mn0 = fmaxf(m0, rm0), mn1 = fmaxf(m1, rm1);
        float a0 = __expf(m0 - mn0), a1 = __expf(m1 - mn1);
        float sum0 = 0.0f, sum1 = 0.0f;
        #pragma unroll
        for (int nb = 0; nb < 8; nb++) {
            s[nb][0] = __expf(s[nb][0] - mn0);
            s[nb][1] = __expf(s[nb][1] - mn0);
            s[nb][2] = __expf(s[nb][2] - mn1);
            s[nb][3] = __expf(s[nb][3] - mn1);
            sum0 += s[nb][0] + s[nb][1];
            sum1 += s[nb][2] + s[nb][3];
        }
        sum0 += __shfl_xor_sync(0xffffffffu, sum0, 1);
        sum0 += __shfl_xor_sync(0xffffffffu, sum0, 2);
        sum1 += __shfl_xor_sync(0xffffffffu, sum1, 1);
        sum1 += __shfl_xor_sync(0xffffffffu, sum1, 2);
        l0 = l0 * a0 + sum0;  m0 = mn0;
        l1 = l1 * a1 + sum1;  m1 = mn1;
        #pragma unroll
        for (int nb = 0; nb < 8; nb++) {
            o[nb][0] *= a0; o[nb][1] *= a0;
            o[nb][2] *= a1; o[nb][3] *= a1;
        }

        // ---- O += P V (3-pass split) ----
        #pragma unroll
        for (int kb = 0; kb < 4; kb++) {
            __nv_bfloat162 h0 = __floats2bfloat162_rn(s[2*kb][0],   s[2*kb][1]);
            __nv_bfloat162 h1 = __floats2bfloat162_rn(s[2*kb][2],   s[2*kb][3]);
            __nv_bfloat162 h2 = __floats2bfloat162_rn(s[2*kb+1][0], s[2*kb+1][1]);
            __nv_bfloat162 h3 = __floats2bfloat162_rn(s[2*kb+1][2], s[2*kb+1][3]);
            __nv_bfloat162 e0 = __floats2bfloat162_rn(
                s[2*kb][0]   - __bfloat162float(h0.x), s[2*kb][1]   - __bfloat162float(h0.y));
            __nv_bfloat162 e1 = __floats2bfloat162_rn(
                s[2*kb][2]   - __bfloat162float(h1.x), s[2*kb][3]   - __bfloat162float(h1.y));
            __nv_bfloat162 e2 = __floats2bfloat162_rn(
                s[2*kb+1][0] - __bfloat162float(h2.x), s[2*kb+1][1] - __bfloat162float(h2.y));
            __nv_bfloat162 e3 = __floats2bfloat162_rn(
                s[2*kb+1][2] - __bfloat162float(h3.x), s[2*kb+1][3] - __bfloat162float(h3.y));
            uint32_t ph[4] = { *(uint32_t*)&h0, *(uint32_t*)&h1, *(uint32_t*)&h2, *(uint32_t*)&h3 };
            uint32_t pl[4] = { *(uint32_t*)&e0, *(uint32_t*)&e1, *(uint32_t*)&e2, *(uint32_t*)&e3 };

            #pragma unroll
            for (int nb = 0; nb < 8; nb++) {
                uint32_t off = (kb * 16 + (lane & 15)) * FSTR + nb * 16;
                uint32_t bvh0, bvh1, bvl0, bvl1;
                LDSM_X2T(bvh0, bvh1, Vh + off);
                LDSM_X2T(bvl0, bvl1, Vl + off);
                MMA_BF16_2(o[nb], ph, bvh0, bvh1);
                MMA_BF16_2(o[nb], pl, bvh0, bvh1);
                MMA_BF16_2(o[nb], ph, bvl0, bvl1);
            }
        }
    }

    // ---- epilogue ----
    float inv0 = 1.0f / l0, inv1 = 1.0f / l1;
    float* base = ob + ((size_t)(b * SS + q0 + row_loc0)) * DD + h * DK + (lane & 3) * 2;
    #pragma unroll
    for (int nb = 0; nb < 8; nb++) {
        *(float2*)(base + nb * 8)          = make_float2(o[nb][0] * inv0, o[nb][1] * inv0);
        *(float2*)(base + 8 * DD + nb * 8) = make_float2(o[nb][2] * inv1, o[nb][3] * inv1);
    }
}

// ---------------- launch -----------------------------------------------------
extern "C" void kernel_launch(void* const* d_in, const int* in_sizes, int n_in,
                              void* d_out, int out_size)
{
    const float* Q  = (const float*)d_in[0];
    const float* K  = (const float*)d_in[1];
    const float* V  = (const float*)d_in[2];
    // d_in[3] = mask (causal by construction; handled analytically)
    const float* Wq = (const float*)d_in[4];
    const float* bq = (const float*)d_in[5];
    const float* Wk = (const float*)d_in[6];
    const float* bk = (const float*)d_in[7];
    const float* Wv = (const float*)d_in[8];
    const float* bv = (const float*)d_in[9];
    const float* Wo = (const float*)d_in[10];
    const float* bo = (const float*)d_in[11];

    float* ga;
    __nv_bfloat16 *qh, *ql, *kh, *kl, *vh, *vl, *ahi, *alo, *whi, *wlo;
    cudaGetSymbolAddress((void**)&ga,  g_attn);
    cudaGetSymbolAddress((void**)&qh,  g_qh);
    cudaGetSymbolAddress((void**)&ql,  g_ql);
    cudaGetSymbolAddress((void**)&kh,  g_kh);
    cudaGetSymbolAddress((void**)&kl,  g_kl);
    cudaGetSymbolAddress((void**)&vh,  g_vh);
    cudaGetSymbolAddress((void**)&vl,  g_vl);
    cudaGetSymbolAddress((void**)&ahi, g_act_hi);
    cudaGetSymbolAddress((void**)&alo, g_act_lo);
    cudaGetSymbolAddress((void**)&whi, g_w_hi);
    cudaGetSymbolAddress((void**)&wlo, g_w_lo);

    cudaFuncSetAttribute(gemm_mma,  cudaFuncAttributeMaxDynamicSharedMemorySize, GEMM_SMEM);
    cudaFuncSetAttribute(flash_mma, cudaFuncAttributeMaxDynamicSharedMemorySize, FLASH_SMEM);

    const int nAct4 = MR * DD / 4;
    const int nW4   = DD * DD / 4;
    dim3 gemmGrid(DD / 128, MR / 128);

    // Q projection (scores scale 1/8 folded into epilogue)
    split_f32<<<(nAct4 + 255) / 256, 256>>>(Q, ahi, alo, nAct4);
    split_f32<<<(nW4 + 255) / 256, 256>>>(Wq, whi, wlo, nW4);
    gemm_mma<<<gemmGrid, 256, GEMM_SMEM>>>(ahi, alo, whi, wlo, bq, nullptr, qh, ql, 0.125f);
    // K projection
    split_f32<<<(nAct4 + 255) / 256, 256>>>(K, ahi, alo, nAct4);
    split_f32<<<(nW4 + 255) / 256, 256>>>(Wk, whi, wlo, nW4);
    gemm_mma<<<gemmGrid, 256, GEMM_SMEM>>>(ahi, alo, whi, wlo, bk, nullptr, kh, kl, 1.0f);
    // V projection
    split_f32<<<(nAct4 + 255) / 256, 256>>>(V, ahi, alo, nAct4);
    split_f32<<<(nW4 + 255) / 256, 256>>>(Wv, whi, wlo, nW4);
    gemm_mma<<<gemmGrid, 256, GEMM_SMEM>>>(ahi, alo, whi, wlo, bv, nullptr, vh, vl, 1.0f);

    // attention (tensor-core flash)
    dim3 attnGrid(SS / 64, BB * HH);
    flash_mma<<<attnGrid, 128, FLASH_SMEM>>>(qh, ql, kh, kl, vh, vl, ga);

    // output projection (fp32 out)
    split_f32<<<(nAct4 + 255) / 256, 256>>>(ga, ahi, alo, nAct4);
    split_f32<<<(nW4 + 255) / 256, 256>>>(Wo, whi, wlo, nW4);
    gemm_mma<<<gemmGrid, 256, GEMM_SMEM>>>(ahi, alo, whi, wlo, bo, (float*)d_out, nullptr, nullptr, 1.0f);
}

// round 5
// speedup vs baseline: 6.3667x; 1.6187x over previous
#include <cuda_runtime.h>
#include <cuda_fp16.h>
#include <cstdint>

#define BB 2
#define SS 2048
#define DD 1024
#define HH 16
#define DK 64
#define MR (BB*SS)   // 4096 rows

// ---------------- scratch (device globals; no allocation allowed) ------------
// act hi/lo staging (reused sequentially; also holds flash O hi/lo for O-proj)
__device__ __align__(16) __half g_act_hi[(size_t)MR * DD];
__device__ __align__(16) __half g_act_lo[(size_t)MR * DD];
__device__ __align__(16) __half g_w16[(size_t)DD * DD];
__device__ __align__(16) __half g_q16[(size_t)MR * DD];
__device__ __align__(16) __half g_k16[(size_t)MR * DD];
__device__ __align__(16) __half g_v16[(size_t)MR * DD];

// ====================== helpers ==============================================
__device__ __forceinline__ uint32_t smem_u32(const void* p) {
    uint32_t a;
    asm("{ .reg .u64 t; cvta.to.shared.u64 t, %1; cvt.u32.u64 %0, t; }" : "=r"(a) : "l"(p));
    return a;
}
#define CP_ASYNC16(dst, src) \
    asm volatile("cp.async.cg.shared.global [%0], [%1], 16;" :: "r"(dst), "l"(src) : "memory")
#define CP_COMMIT() asm volatile("cp.async.commit_group;" ::: "memory")
#define CP_WAIT1()  asm volatile("cp.async.wait_group 1;" ::: "memory")
#define CP_WAIT0()  asm volatile("cp.async.wait_group 0;" ::: "memory")

#define LDSM_X4(r0,r1,r2,r3, addr) \
    asm volatile("ldmatrix.sync.aligned.m8n8.x4.shared.b16 {%0,%1,%2,%3}, [%4];" \
        : "=r"(r0), "=r"(r1), "=r"(r2), "=r"(r3) : "r"(addr))
#define LDSM_X2(r0,r1, addr) \
    asm volatile("ldmatrix.sync.aligned.m8n8.x2.shared.b16 {%0,%1}, [%2];" \
        : "=r"(r0), "=r"(r1) : "r"(addr))
#define LDSM_X2T(r0,r1, addr) \
    asm volatile("ldmatrix.sync.aligned.m8n8.x2.trans.shared.b16 {%0,%1}, [%2];" \
        : "=r"(r0), "=r"(r1) : "r"(addr))
#define MMA_F16(d, a, b0, b1) \
    asm volatile("mma.sync.aligned.m16n8k16.row.col.f32.f16.f16.f32 " \
        "{%0,%1,%2,%3}, {%4,%5,%6,%7}, {%8,%9}, {%0,%1,%2,%3};" \
        : "+f"((d)[0]), "+f"((d)[1]), "+f"((d)[2]), "+f"((d)[3]) \
        : "r"((a)[0]), "r"((a)[1]), "r"((a)[2]), "r"((a)[3]), \
          "r"(b0), "r"(b1))

// ====================== fp32 -> fp16 hi/lo split =============================
__global__ __launch_bounds__(256) void split_f32(
    const float* __restrict__ in, __half* __restrict__ hi,
    __half* __restrict__ lo, int n4)
{
    int i = blockIdx.x * 256 + threadIdx.x;
    if (i >= n4) return;
    float4 x = ((const float4*)in)[i];
    __half h0 = __float2half_rn(x.x), h1 = __float2half_rn(x.y);
    __half h2 = __float2half_rn(x.z), h3 = __float2half_rn(x.w);
    __half l0 = __float2half_rn(x.x - __half2float(h0));
    __half l1 = __float2half_rn(x.y - __half2float(h1));
    __half l2 = __float2half_rn(x.z - __half2float(h2));
    __half l3 = __float2half_rn(x.w - __half2float(h3));
    __half2* hp = (__half2*)hi;
    __half2* lp = (__half2*)lo;
    hp[2*i]   = __halves2half2(h0, h1);
    hp[2*i+1] = __halves2half2(h2, h3);
    lp[2*i]   = __halves2half2(l0, l1);
    lp[2*i+1] = __halves2half2(l2, l3);
}

// ====================== fp32 -> fp16 convert (weights) =======================
__global__ __launch_bounds__(256) void conv_f16(
    const float* __restrict__ in, __half* __restrict__ out, int n4)
{
    int i = blockIdx.x * 256 + threadIdx.x;
    if (i >= n4) return;
    float4 x = ((const float4*)in)[i];
    __half2* op = (__half2*)out;
    op[2*i]   = __floats2half2_rn(x.x, x.y);
    op[2*i+1] = __floats2half2_rn(x.z, x.w);
}

// ====================== 2-pass fp16 GEMM: C = (Ahi+Alo)*W^T + bias ===========
// 128x128 tile/CTA, BK=32, cp.async double-buffered, 8 warps (2m x 4n).
// B-fragments loaded once per ks and reused across both passes.
#define TSTRIDE 80
#define TILE_B  (128 * TSTRIDE)          // 10240 B
#define BUF_B   (3 * TILE_B)             // Ahi, Alo, W
#define GEMM_SMEM (2 * BUF_B)            // 61440 B

__global__ __launch_bounds__(256, 2) void gemm_mma(
    const __half* __restrict__ Ahi, const __half* __restrict__ Alo,
    const __half* __restrict__ W,
    const float* __restrict__ bias, float* __restrict__ Cf32,
    __half* __restrict__ C16, float scale)
{
    extern __shared__ char smem[];
    const uint32_t sbase = smem_u32(smem);
    const int t    = threadIdx.x;
    const int lane = t & 31;
    const int wid  = t >> 5;
    const int wm   = wid & 1;
    const int wn   = wid >> 1;
    const int rowBase = blockIdx.y << 7;
    const int colBase = blockIdx.x << 7;

    const __half* srcs[3] = {
        Ahi + (size_t)rowBase * DD, Alo + (size_t)rowBase * DD,
        W + (size_t)colBase * DD };

    const int r0 = t >> 2;
    const int r1 = 64 + (t >> 2);
    const int sg = t & 3;

    float acc[4][4][4];
    #pragma unroll
    for (int i = 0; i < 4; i++)
        #pragma unroll
        for (int j = 0; j < 4; j++)
            #pragma unroll
            for (int e = 0; e < 4; e++) acc[i][j][e] = 0.0f;

    {
        #pragma unroll
        for (int tile = 0; tile < 3; tile++) {
            const __half* s = srcs[tile] + sg * 8;
            uint32_t d = sbase + tile * TILE_B + sg * 16;
            CP_ASYNC16(d + r0 * TSTRIDE, s + (size_t)r0 * DD);
            CP_ASYNC16(d + r1 * TSTRIDE, s + (size_t)r1 * DD);
        }
        CP_COMMIT();
    }

    for (int c = 0; c < 32; c++) {
        if (c + 1 < 32) {
            const uint32_t base = sbase + ((c + 1) & 1) * BUF_B;
            const int k0 = (c + 1) * 32;
            #pragma unroll
            for (int tile = 0; tile < 3; tile++) {
                const __half* s = srcs[tile] + k0 + sg * 8;
                uint32_t d = base + tile * TILE_B + sg * 16;
                CP_ASYNC16(d + r0 * TSTRIDE, s + (size_t)r0 * DD);
                CP_ASYNC16(d + r1 * TSTRIDE, s + (size_t)r1 * DD);
            }
            CP_COMMIT();
            CP_WAIT1();
        } else {
            CP_WAIT0();
        }
        __syncthreads();

        const uint32_t base = sbase + (c & 1) * BUF_B;
        const uint32_t aHiT = base;
        const uint32_t aLoT = base + TILE_B;
        const uint32_t bT   = base + 2 * TILE_B;
        #pragma unroll
        for (int ks = 0; ks < 2; ks++) {
            // B fragments (shared by both passes)
            uint32_t b[4][2];
            const int l = lane & 15;
            #pragma unroll
            for (int nt = 0; nt < 4; nt++) {
                uint32_t addr = bT
                    + (wn * 32 + nt * 8 + (l & 7)) * TSTRIDE
                    + (ks * 16 + ((l >> 3) & 1) * 8) * 2;
                LDSM_X2(b[nt][0], b[nt][1], addr);
            }
            // pass 1: Ahi
            uint32_t ah[4][4];
            #pragma unroll
            for (int mt = 0; mt < 4; mt++) {
                uint32_t addr = aHiT
                    + (wm * 64 + mt * 16 + (lane & 15)) * TSTRIDE
                    + (ks * 16 + (lane >> 4) * 8) * 2;
                LDSM_X4(ah[mt][0], ah[mt][1], ah[mt][2], ah[mt][3], addr);
            }
            #pragma unroll
            for (int mt = 0; mt < 4; mt++)
                #pragma unroll
                for (int nt = 0; nt < 4; nt++)
                    MMA_F16(acc[mt][nt], ah[mt], b[nt][0], b[nt][1]);
            // pass 2: Alo
            uint32_t al[4][4];
            #pragma unroll
            for (int mt = 0; mt < 4; mt++) {
                uint32_t addr = aLoT
                    + (wm * 64 + mt * 16 + (lane & 15)) * TSTRIDE
                    + (ks * 16 + (lane >> 4) * 8) * 2;
                LDSM_X4(al[mt][0], al[mt][1], al[mt][2], al[mt][3], addr);
            }
            #pragma unroll
            for (int mt = 0; mt < 4; mt++)
                #pragma unroll
                for (int nt = 0; nt < 4; nt++)
                    MMA_F16(acc[mt][nt], al[mt], b[nt][0], b[nt][1]);
        }
        __syncthreads();
    }

    const int g   = lane >> 2;
    const int tig = lane & 3;
    #pragma unroll
    for (int mt = 0; mt < 4; mt++) {
        const int row = rowBase + wm * 64 + mt * 16 + g;
        #pragma unroll
        for (int nt = 0; nt < 4; nt++) {
            const int col = colBase + wn * 32 + nt * 8 + 2 * tig;
            float2 bv = *(const float2*)(bias + col);
            float c00 = (acc[mt][nt][0] + bv.x) * scale;
            float c01 = (acc[mt][nt][1] + bv.y) * scale;
            float c10 = (acc[mt][nt][2] + bv.x) * scale;
            float c11 = (acc[mt][nt][3] + bv.y) * scale;
            if (Cf32) {
                *(float2*)(Cf32 + (size_t)row * DD + col)       = make_float2(c00, c01);
                *(float2*)(Cf32 + (size_t)(row + 8) * DD + col) = make_float2(c10, c11);
            } else {
                *(__half2*)(C16 + (size_t)row * DD + col)       = __floats2half2_rn(c00, c01);
                *(__half2*)(C16 + (size_t)(row + 8) * DD + col) = __floats2half2_rn(c10, c11);
            }
        }
    }
}

// ====================== Flash attention, single-pass fp16 ====================
// grid=(S/64, B*H), 128 threads (4 warps). BK=64, DK=64.
// SMEM: Q + 2 bufs x {K,V}, stride 144B. Epilogue emits O hi/lo fp16.
#define FSTR 144
#define FTILE (64 * FSTR)                 // 9216 B
#define FLASH_SMEM (FTILE + 2 * 2 * FTILE)   // 46080 B

__global__ __launch_bounds__(128) void flash_mma(
    const __half* __restrict__ q16, const __half* __restrict__ k16,
    const __half* __restrict__ v16,
    __half* __restrict__ ohi, __half* __restrict__ olo)
{
    extern __shared__ char fsm[];
    const uint32_t sb = smem_u32(fsm);
    const int t = threadIdx.x, lane = t & 31, w = t >> 5;
    const int qt = blockIdx.x, bh = blockIdx.y, b = bh >> 4, h = bh & 15;
    const int q0 = qt << 6;

    const uint32_t Qs = sb;
    const uint32_t KV0 = sb + FTILE;

    const size_t hoff = (size_t)h * DK;
    const __half* qsrc = q16 + (size_t)(b * SS + q0) * DD + hoff;

    // prologue: Q tile + KV(kt=0)
    #pragma unroll
    for (int it = 0; it < 4; it++) {
        int idx = it * 128 + t, row = idx >> 3, sg = idx & 7;
        CP_ASYNC16(Qs + row * FSTR + sg * 16, qsrc + (size_t)row * DD + sg * 8);
    }
    {
        const size_t base0 = (size_t)(b * SS) * DD + hoff;
        const __half* src[2] = { k16 + base0, v16 + base0 };
        #pragma unroll
        for (int ti = 0; ti < 2; ti++) {
            uint32_t dstT = KV0 + ti * FTILE;
            #pragma unroll
            for (int it = 0; it < 4; it++) {
                int idx = it * 128 + t, row = idx >> 3, sg = idx & 7;
                CP_ASYNC16(dstT + row * FSTR + sg * 16, src[ti] + (size_t)row * DD + sg * 8);
            }
        }
    }
    CP_COMMIT();

    float o[8][4];
    #pragma unroll
    for (int nb = 0; nb < 8; nb++)
        #pragma unroll
        for (int e = 0; e < 4; e++) o[nb][e] = 0.0f;
    float m0 = -1e30f, m1 = -1e30f, l0 = 0.0f, l1 = 0.0f;

    uint32_t qa[4][4];
    const int row_loc0 = w * 16 + (lane >> 2);

    for (int kt = 0; kt <= qt; kt++) {
        if (kt > 0) __syncthreads();
        if (kt < qt) {
            const size_t base = (size_t)(b * SS + ((kt + 1) << 6)) * DD + hoff;
            const __half* src[2] = { k16 + base, v16 + base };
            const uint32_t bufb = KV0 + ((kt + 1) & 1) * 2 * FTILE;
            #pragma unroll
            for (int ti = 0; ti < 2; ti++) {
                uint32_t dstT = bufb + ti * FTILE;
                #pragma unroll
                for (int it = 0; it < 4; it++) {
                    int idx = it * 128 + t, row = idx >> 3, sg = idx & 7;
                    CP_ASYNC16(dstT + row * FSTR + sg * 16, src[ti] + (size_t)row * DD + sg * 8);
                }
            }
            CP_COMMIT();
            CP_WAIT1();
        } else {
            CP_WAIT0();
        }
        __syncthreads();

        if (kt == 0) {
            #pragma unroll
            for (int ks = 0; ks < 4; ks++) {
                uint32_t addr = Qs + (w * 16 + (lane & 15)) * FSTR + ks * 32 + (lane >> 4) * 16;
                LDSM_X4(qa[ks][0], qa[ks][1], qa[ks][2], qa[ks][3], addr);
            }
        }

        const uint32_t Kh = KV0 + (kt & 1) * 2 * FTILE;
        const uint32_t Vh = Kh + FTILE;

        // ---- S = QK^T ----
        float s[8][4];
        #pragma unroll
        for (int nb = 0; nb < 8; nb++)
            #pragma unroll
            for (int e = 0; e < 4; e++) s[nb][e] = 0.0f;

        #pragma unroll
        for (int ks = 0; ks < 4; ks++) {
            #pragma unroll
            for (int nb2 = 0; nb2 < 4; nb2++) {
                uint32_t off = (nb2 * 16 + ((lane >> 4) << 3) + (lane & 7)) * FSTR
                             + ks * 32 + ((lane >> 3) & 1) * 16;
                uint32_t kf[4];
                LDSM_X4(kf[0], kf[1], kf[2], kf[3], Kh + off);
                MMA_F16(s[2*nb2],   qa[ks], kf[0], kf[1]);
                MMA_F16(s[2*nb2+1], qa[ks], kf[2], kf[3]);
            }
        }

        // ---- causal mask (diagonal tile) ----
        if (kt == qt) {
            #pragma unroll
            for (int nb = 0; nb < 8; nb++) {
                int c0 = nb * 8 + (lane & 3) * 2;
                if (c0     > row_loc0)     s[nb][0] = -1e30f;
                if (c0 + 1 > row_loc0)     s[nb][1] = -1e30f;
                if (c0     > row_loc0 + 8) s[nb][2] = -1e30f;
                if (c0 + 1 > row_loc0 + 8) s[nb][3] = -1e30f;
            }
        }

        // ---- online softmax ----
        float rm0 = -1e30f, rm1 = -1e30f;
        #pragma unroll
        for (int nb = 0; nb < 8; nb++) {
            rm0 = fmaxf(rm0, fmaxf(s[nb][0], s[nb][1]));
            rm1 = fmaxf(rm1, fmaxf(s[nb][2], s[nb][3]));
        }
        rm0 = fmaxf(rm0, __shfl_xor_sync(0xffffffffu, rm0, 1));
        rm0 = fmaxf(rm0, __shfl_xor_sync(0xffffffffu, rm0, 2));
        rm1 = fmaxf(rm1, __shfl_xor_sync(0xffffffffu, rm1, 1));
        rm1 = fmaxf(rm1, __shfl_xor_sync(0xffffffffu, rm1, 2));
        float mn0 = fmaxf(m0, rm0), mn1 = fmaxf(m1, rm1);
        float a0 = __expf(m0 - mn0), a1 = __expf(m1 - mn1);
        float sum0 = 0.0f, sum1 = 0.0f;
        #pragma unroll
        for (int nb = 0; nb < 8; nb++) {
            s[nb][0] = __expf(s[nb][0] - mn0);
            s[nb][1] = __expf(s[nb][1] - mn0);
            s[nb][2] = __expf(s[nb][2] - mn1);
            s[nb][3] = __expf(s[nb][3] - mn1);
            sum0 += s[nb][0] + s[nb][1];
            sum1 += s[nb][2] + s[nb][3];
        }
        sum0 += __shfl_xor_sync(0xffffffffu, sum0, 1);
        sum0 += __shfl_xor_sync(0xffffffffu, sum0, 2);
        sum1 += __shfl_xor_sync(0xffffffffu, sum1, 1);
        sum1 += __shfl_xor_sync(0xffffffffu, sum1, 2);
        l0 = l0 * a0 + sum0;  m0 = mn0;
        l1 = l1 * a1 + sum1;  m1 = mn1;
        #pragma unroll
        for (int nb = 0; nb < 8; nb++) {
            o[nb][0] *= a0; o[nb][1] *= a0;
            o[nb][2] *= a1; o[nb][3] *= a1;
        }

        // ---- O += P V ----
        #pragma unroll
        for (int kb = 0; kb < 4; kb++) {
            __half2 p0 = __floats2half2_rn(s[2*kb][0],   s[2*kb][1]);
            __half2 p1 = __floats2half2_rn(s[2*kb][2],   s[2*kb][3]);
            __half2 p2 = __floats2half2_rn(s[2*kb+1][0], s[2*kb+1][1]);
            __half2 p3 = __floats2half2_rn(s[2*kb+1][2], s[2*kb+1][3]);
            uint32_t ph[4] = { *(uint32_t*)&p0, *(uint32_t*)&p1,
                               *(uint32_t*)&p2, *(uint32_t*)&p3 };
            #pragma unroll
            for (int nb = 0; nb < 8; nb++) {
                uint32_t off = (kb * 16 + (lane & 15)) * FSTR + nb * 16;
                uint32_t v0, v1;
                LDSM_X2T(v0, v1, Vh + off);
                MMA_F16(o[nb], ph, v0, v1);
            }
        }
    }

    // ---- epilogue: normalize + split to fp16 hi/lo ----
    float inv0 = 1.0f / l0, inv1 = 1.0f / l1;
    const size_t rbase = (size_t)(b * SS + q0 + row_loc0) * DD + h * DK + (lane & 3) * 2;
    #pragma unroll
    for (int nb = 0; nb < 8; nb++) {
        float x0 = o[nb][0] * inv0, x1 = o[nb][1] * inv0;
        float y0 = o[nb][2] * inv1, y1 = o[nb][3] * inv1;
        __half2 xh = __floats2half2_rn(x0, x1);
        __half2 yh = __floats2half2_rn(y0, y1);
        __half2 xl = __floats2half2_rn(x0 - __half2float(__low2half(xh)),
                                       x1 - __half2float(__high2half(xh)));
        __half2 yl = __floats2half2_rn(y0 - __half2float(__low2half(yh)),
                                       y1 - __half2float(__high2half(yh)));
        *(__half2*)(ohi + rbase + nb * 8)          = xh;
        *(__half2*)(olo + rbase + nb * 8)          = xl;
        *(__half2*)(ohi + rbase + 8 * DD + nb * 8) = yh;
        *(__half2*)(olo + rbase + 8 * DD + nb * 8) = yl;
    }
}

// ---------------- launch -----------------------------------------------------
extern "C" void kernel_launch(void* const* d_in, const int* in_sizes, int n_in,
                              void* d_out, int out_size)
{
    const float* Q  = (const float*)d_in[0];
    const float* K  = (const float*)d_in[1];
    const float* V  = (const float*)d_in[2];
    // d_in[3] = mask (causal by construction; handled analytically)
    const float* Wq = (const float*)d_in[4];
    const float* bq = (const float*)d_in[5];
    const float* Wk = (const float*)d_in[6];
    const float* bk = (const float*)d_in[7];
    const float* Wv = (const float*)d_in[8];
    const float* bv = (const float*)d_in[9];
    const float* Wo = (const float*)d_in[10];
    const float* bo = (const float*)d_in[11];

    __half *ahi, *alo, *w16, *q16, *k16, *v16;
    cudaGetSymbolAddress((void**)&ahi, g_act_hi);
    cudaGetSymbolAddress((void**)&alo, g_act_lo);
    cudaGetSymbolAddress((void**)&w16, g_w16);
    cudaGetSymbolAddress((void**)&q16, g_q16);
    cudaGetSymbolAddress((void**)&k16, g_k16);
    cudaGetSymbolAddress((void**)&v16, g_v16);

    cudaFuncSetAttribute(gemm_mma,  cudaFuncAttributeMaxDynamicSharedMemorySize, GEMM_SMEM);
    cudaFuncSetAttribute(flash_mma, cudaFuncAttributeMaxDynamicSharedMemorySize, FLASH_SMEM);

    const int nAct4 = MR * DD / 4;
    const int nW4   = DD * DD / 4;
    dim3 gemmGrid(DD / 128, MR / 128);

    // Q projection (score scale 1/8 folded into epilogue, incl. bias)
    split_f32<<<(nAct4 + 255) / 256, 256>>>(Q, ahi, alo, nAct4);
    conv_f16<<<(nW4 + 255) / 256, 256>>>(Wq, w16, nW4);
    gemm_mma<<<gemmGrid, 256, GEMM_SMEM>>>(ahi, alo, w16, bq, nullptr, q16, 0.125f);
    // K projection
    split_f32<<<(nAct4 + 255) / 256, 256>>>(K, ahi, alo, nAct4);
    conv_f16<<<(nW4 + 255) / 256, 256>>>(Wk, w16, nW4);
    gemm_mma<<<gemmGrid, 256, GEMM_SMEM>>>(ahi, alo, w16, bk, nullptr, k16, 1.0f);
    // V projection
    split_f32<<<(nAct4 + 255) / 256, 256>>>(V, ahi, alo, nAct4);
    conv_f16<<<(nW4 + 255) / 256, 256>>>(Wv, w16, nW4);
    gemm_mma<<<gemmGrid, 256, GEMM_SMEM>>>(ahi, alo, w16, bv, nullptr, v16, 1.0f);

    // attention (single-pass fp16; epilogue emits O hi/lo into act buffers)
    dim3 attnGrid(SS / 64, BB * HH);
    flash_mma<<<attnGrid, 128, FLASH_SMEM>>>(q16, k16, v16, ahi, alo);

    // output projection (fp32 out)
    conv_f16<<<(nW4 + 255) / 256, 256>>>(Wo, w16, nW4);
    gemm_mma<<<gemmGrid, 256, GEMM_SMEM>>>(ahi, alo, w16, bo, (float*)d_out, nullptr, 1.0f);
}

// round 6
// speedup vs baseline: 8.8481x; 1.3897x over previous
#include <cuda_runtime.h>
#include <cuda_fp16.h>
#include <cstdint>

#define BB 2
#define SS 2048
#define DD 1024
#define HH 16
#define DK 64
#define MR (BB*SS)   // 4096 rows

// ---------------- scratch (device globals; no allocation allowed) ------------
// g_a16: activation staging for each projection; reused as flash O output.
__device__ __align__(16) __half g_a16[(size_t)MR * DD];
__device__ __align__(16) __half g_w16[(size_t)DD * DD];
__device__ __align__(16) __half g_q16[(size_t)MR * DD];
__device__ __align__(16) __half g_k16[(size_t)MR * DD];
__device__ __align__(16) __half g_v16[(size_t)MR * DD];

// ====================== helpers ==============================================
__device__ __forceinline__ uint32_t smem_u32(const void* p) {
    uint32_t a;
    asm("{ .reg .u64 t; cvta.to.shared.u64 t, %1; cvt.u32.u64 %0, t; }" : "=r"(a) : "l"(p));
    return a;
}
#define CP_ASYNC16(dst, src) \
    asm volatile("cp.async.cg.shared.global [%0], [%1], 16;" :: "r"(dst), "l"(src) : "memory")
#define CP_COMMIT() asm volatile("cp.async.commit_group;" ::: "memory")
#define CP_WAIT1()  asm volatile("cp.async.wait_group 1;" ::: "memory")
#define CP_WAIT0()  asm volatile("cp.async.wait_group 0;" ::: "memory")

#define LDSM_X4(r0,r1,r2,r3, addr) \
    asm volatile("ldmatrix.sync.aligned.m8n8.x4.shared.b16 {%0,%1,%2,%3}, [%4];" \
        : "=r"(r0), "=r"(r1), "=r"(r2), "=r"(r3) : "r"(addr))
#define LDSM_X2(r0,r1, addr) \
    asm volatile("ldmatrix.sync.aligned.m8n8.x2.shared.b16 {%0,%1}, [%2];" \
        : "=r"(r0), "=r"(r1) : "r"(addr))
#define LDSM_X2T(r0,r1, addr) \
    asm volatile("ldmatrix.sync.aligned.m8n8.x2.trans.shared.b16 {%0,%1}, [%2];" \
        : "=r"(r0), "=r"(r1) : "r"(addr))
#define MMA_F16(d, a, b0, b1) \
    asm volatile("mma.sync.aligned.m16n8k16.row.col.f32.f16.f16.f32 " \
        "{%0,%1,%2,%3}, {%4,%5,%6,%7}, {%8,%9}, {%0,%1,%2,%3};" \
        : "+f"((d)[0]), "+f"((d)[1]), "+f"((d)[2]), "+f"((d)[3]) \
        : "r"((a)[0]), "r"((a)[1]), "r"((a)[2]), "r"((a)[3]), \
          "r"(b0), "r"(b1))

// ====================== fp32 -> fp16 convert =================================
__global__ __launch_bounds__(256) void conv_f16(
    const float* __restrict__ in, __half* __restrict__ out, int n4)
{
    int i = blockIdx.x * 256 + threadIdx.x;
    if (i >= n4) return;
    float4 x = ((const float4*)in)[i];
    __half2* op = (__half2*)out;
    op[2*i]   = __floats2half2_rn(x.x, x.y);
    op[2*i+1] = __floats2half2_rn(x.z, x.w);
}

// ====================== 1-pass fp16 GEMM: C = A*W^T + bias ===================
// 128x128 tile/CTA, BK=32, cp.async double-buffered, 8 warps (2m x 4n).
#define TSTRIDE 80
#define TILE_B  (128 * TSTRIDE)          // 10240 B
#define BUF_B   (2 * TILE_B)             // A, W
#define GEMM_SMEM (2 * BUF_B)            // 40960 B

__global__ __launch_bounds__(256, 2) void gemm_mma(
    const __half* __restrict__ A16, const __half* __restrict__ W,
    const float* __restrict__ bias, float* __restrict__ Cf32,
    __half* __restrict__ C16, float scale)
{
    extern __shared__ char smem[];
    const uint32_t sbase = smem_u32(smem);
    const int t    = threadIdx.x;
    const int lane = t & 31;
    const int wid  = t >> 5;
    const int wm   = wid & 1;
    const int wn   = wid >> 1;
    const int rowBase = blockIdx.y << 7;
    const int colBase = blockIdx.x << 7;

    const __half* srcs[2] = {
        A16 + (size_t)rowBase * DD, W + (size_t)colBase * DD };

    const int r0 = t >> 2;
    const int r1 = 64 + (t >> 2);
    const int sg = t & 3;

    float acc[4][4][4];
    #pragma unroll
    for (int i = 0; i < 4; i++)
        #pragma unroll
        for (int j = 0; j < 4; j++)
            #pragma unroll
            for (int e = 0; e < 4; e++) acc[i][j][e] = 0.0f;

    {
        #pragma unroll
        for (int tile = 0; tile < 2; tile++) {
            const __half* s = srcs[tile] + sg * 8;
            uint32_t d = sbase + tile * TILE_B + sg * 16;
            CP_ASYNC16(d + r0 * TSTRIDE, s + (size_t)r0 * DD);
            CP_ASYNC16(d + r1 * TSTRIDE, s + (size_t)r1 * DD);
        }
        CP_COMMIT();
    }

    for (int c = 0; c < 32; c++) {
        if (c + 1 < 32) {
            const uint32_t base = sbase + ((c + 1) & 1) * BUF_B;
            const int k0 = (c + 1) * 32;
            #pragma unroll
            for (int tile = 0; tile < 2; tile++) {
                const __half* s = srcs[tile] + k0 + sg * 8;
                uint32_t d = base + tile * TILE_B + sg * 16;
                CP_ASYNC16(d + r0 * TSTRIDE, s + (size_t)r0 * DD);
                CP_ASYNC16(d + r1 * TSTRIDE, s + (size_t)r1 * DD);
            }
            CP_COMMIT();
            CP_WAIT1();
        } else {
            CP_WAIT0();
        }
        __syncthreads();

        const uint32_t base = sbase + (c & 1) * BUF_B;
        const uint32_t aT = base;
        const uint32_t bT = base + TILE_B;
        #pragma unroll
        for (int ks = 0; ks < 2; ks++) {
            uint32_t b[4][2];
            const int l = lane & 15;
            #pragma unroll
            for (int nt = 0; nt < 4; nt++) {
                uint32_t addr = bT
                    + (wn * 32 + nt * 8 + (l & 7)) * TSTRIDE
                    + (ks * 16 + ((l >> 3) & 1) * 8) * 2;
                LDSM_X2(b[nt][0], b[nt][1], addr);
            }
            uint32_t ah[4][4];
            #pragma unroll
            for (int mt = 0; mt < 4; mt++) {
                uint32_t addr = aT
                    + (wm * 64 + mt * 16 + (lane & 15)) * TSTRIDE
                    + (ks * 16 + (lane >> 4) * 8) * 2;
                LDSM_X4(ah[mt][0], ah[mt][1], ah[mt][2], ah[mt][3], addr);
            }
            #pragma unroll
            for (int mt = 0; mt < 4; mt++)
                #pragma unroll
                for (int nt = 0; nt < 4; nt++)
                    MMA_F16(acc[mt][nt], ah[mt], b[nt][0], b[nt][1]);
        }
        __syncthreads();
    }

    const int g   = lane >> 2;
    const int tig = lane & 3;
    #pragma unroll
    for (int mt = 0; mt < 4; mt++) {
        const int row = rowBase + wm * 64 + mt * 16 + g;
        #pragma unroll
        for (int nt = 0; nt < 4; nt++) {
            const int col = colBase + wn * 32 + nt * 8 + 2 * tig;
            float2 bv = *(const float2*)(bias + col);
            float c00 = (acc[mt][nt][0] + bv.x) * scale;
            float c01 = (acc[mt][nt][1] + bv.y) * scale;
            float c10 = (acc[mt][nt][2] + bv.x) * scale;
            float c11 = (acc[mt][nt][3] + bv.y) * scale;
            if (Cf32) {
                *(float2*)(Cf32 + (size_t)row * DD + col)       = make_float2(c00, c01);
                *(float2*)(Cf32 + (size_t)(row + 8) * DD + col) = make_float2(c10, c11);
            } else {
                *(__half2*)(C16 + (size_t)row * DD + col)       = __floats2half2_rn(c00, c01);
                *(__half2*)(C16 + (size_t)(row + 8) * DD + col) = __floats2half2_rn(c10, c11);
            }
        }
    }
}

// ====================== Flash attention, single-pass fp16 ====================
// grid=(S/64, B*H), 128 threads (4 warps). BK=64, DK=64.
// SMEM: Q + 2 bufs x {K,V}, stride 144B. Epilogue emits fp16 O.
#define FSTR 144
#define FTILE (64 * FSTR)                 // 9216 B
#define FLASH_SMEM (FTILE + 2 * 2 * FTILE)   // 46080 B

__global__ __launch_bounds__(128) void flash_mma(
    const __half* __restrict__ q16, const __half* __restrict__ k16,
    const __half* __restrict__ v16, __half* __restrict__ o16)
{
    extern __shared__ char fsm[];
    const uint32_t sb = smem_u32(fsm);
    const int t = threadIdx.x, lane = t & 31, w = t >> 5;
    const int qt = blockIdx.x, bh = blockIdx.y, b = bh >> 4, h = bh & 15;
    const int q0 = qt << 6;

    const uint32_t Qs = sb;
    const uint32_t KV0 = sb + FTILE;

    const size_t hoff = (size_t)h * DK;
    const __half* qsrc = q16 + (size_t)(b * SS + q0) * DD + hoff;

    #pragma unroll
    for (int it = 0; it < 4; it++) {
        int idx = it * 128 + t, row = idx >> 3, sg = idx & 7;
        CP_ASYNC16(Qs + row * FSTR + sg * 16, qsrc + (size_t)row * DD + sg * 8);
    }
    {
        const size_t base0 = (size_t)(b * SS) * DD + hoff;
        const __half* src[2] = { k16 + base0, v16 + base0 };
        #pragma unroll
        for (int ti = 0; ti < 2; ti++) {
            uint32_t dstT = KV0 + ti * FTILE;
            #pragma unroll
            for (int it = 0; it < 4; it++) {
                int idx = it * 128 + t, row = idx >> 3, sg = idx & 7;
                CP_ASYNC16(dstT + row * FSTR + sg * 16, src[ti] + (size_t)row * DD + sg * 8);
            }
        }
    }
    CP_COMMIT();

    float o[8][4];
    #pragma unroll
    for (int nb = 0; nb < 8; nb++)
        #pragma unroll
        for (int e = 0; e < 4; e++) o[nb][e] = 0.0f;
    float m0 = -1e30f, m1 = -1e30f, l0 = 0.0f, l1 = 0.0f;

    uint32_t qa[4][4];
    const int row_loc0 = w * 16 + (lane >> 2);

    for (int kt = 0; kt <= qt; kt++) {
        if (kt > 0) __syncthreads();
        if (kt < qt) {
            const size_t base = (size_t)(b * SS + ((kt + 1) << 6)) * DD + hoff;
            const __half* src[2] = { k16 + base, v16 + base };
            const uint32_t bufb = KV0 + ((kt + 1) & 1) * 2 * FTILE;
            #pragma unroll
            for (int ti = 0; ti < 2; ti++) {
                uint32_t dstT = bufb + ti * FTILE;
                #pragma unroll
                for (int it = 0; it < 4; it++) {
                    int idx = it * 128 + t, row = idx >> 3, sg = idx & 7;
                    CP_ASYNC16(dstT + row * FSTR + sg * 16, src[ti] + (size_t)row * DD + sg * 8);
                }
            }
            CP_COMMIT();
            CP_WAIT1();
        } else {
            CP_WAIT0();
        }
        __syncthreads();

        if (kt == 0) {
            #pragma unroll
            for (int ks = 0; ks < 4; ks++) {
                uint32_t addr = Qs + (w * 16 + (lane & 15)) * FSTR + ks * 32 + (lane >> 4) * 16;
                LDSM_X4(qa[ks][0], qa[ks][1], qa[ks][2], qa[ks][3], addr);
            }
        }

        const uint32_t Kh = KV0 + (kt & 1) * 2 * FTILE;
        const uint32_t Vh = Kh + FTILE;

        // ---- S = QK^T ----
        float s[8][4];
        #pragma unroll
        for (int nb = 0; nb < 8; nb++)
            #pragma unroll
            for (int e = 0; e < 4; e++) s[nb][e] = 0.0f;

        #pragma unroll
        for (int ks = 0; ks < 4; ks++) {
            #pragma unroll
            for (int nb2 = 0; nb2 < 4; nb2++) {
                uint32_t off = (nb2 * 16 + ((lane >> 4) << 3) + (lane & 7)) * FSTR
                             + ks * 32 + ((lane >> 3) & 1) * 16;
                uint32_t kf[4];
                LDSM_X4(kf[0], kf[1], kf[2], kf[3], Kh + off);
                MMA_F16(s[2*nb2],   qa[ks], kf[0], kf[1]);
                MMA_F16(s[2*nb2+1], qa[ks], kf[2], kf[3]);
            }
        }

        // ---- causal mask (diagonal tile) ----
        if (kt == qt) {
            #pragma unroll
            for (int nb = 0; nb < 8; nb++) {
                int c0 = nb * 8 + (lane & 3) * 2;
                if (c0     > row_loc0)     s[nb][0] = -1e30f;
                if (c0 + 1 > row_loc0)     s[nb][1] = -1e30f;
                if (c0     > row_loc0 + 8) s[nb][2] = -1e30f;
                if (c0 + 1 > row_loc0 + 8) s[nb][3] = -1e30f;
            }
        }

        // ---- online softmax ----
        float rm0 = -1e30f, rm1 = -1e30f;
        #pragma unroll
        for (int nb = 0; nb < 8; nb++) {
            rm0 = fmaxf(rm0, fmaxf(s[nb][0], s[nb][1]));
            rm1 = fmaxf(rm1, fmaxf(s[nb][2], s[nb][3]));
        }
        rm0 = fmaxf(rm0, __shfl_xor_sync(0xffffffffu, rm0, 1));
        rm0 = fmaxf(rm0, __shfl_xor_sync(0xffffffffu, rm0, 2));
        rm1 = fmaxf(rm1, __shfl_xor_sync(0xffffffffu, rm1, 1));
        rm1 = fmaxf(rm1, __shfl_xor_sync(0xffffffffu, rm1, 2));
        float mn0 = fmaxf(m0, rm0), mn1 = fmaxf(m1, rm1);
        float a0 = __expf(m0 - mn0), a1 = __expf(m1 - mn1);
        float sum0 = 0.0f, sum1 = 0.0f;
        #pragma unroll
        for (int nb = 0; nb < 8; nb++) {
            s[nb][0] = __expf(s[nb][0] - mn0);
            s[nb][1] = __expf(s[nb][1] - mn0);
            s[nb][2] = __expf(s[nb][2] - mn1);
            s[nb][3] = __expf(s[nb][3] - mn1);
            sum0 += s[nb][0] + s[nb][1];
            sum1 += s[nb][2] + s[nb][3];
        }
        sum0 += __shfl_xor_sync(0xffffffffu, sum0, 1);
        sum0 += __shfl_xor_sync(0xffffffffu, sum0, 2);
        sum1 += __shfl_xor_sync(0xffffffffu, sum1, 1);
        sum1 += __shfl_xor_sync(0xffffffffu, sum1, 2);
        l0 = l0 * a0 + sum0;  m0 = mn0;
        l1 = l1 * a1 + sum1;  m1 = mn1;
        #pragma unroll
        for (int nb = 0; nb < 8; nb++) {
            o[nb][0] *= a0; o[nb][1] *= a0;
            o[nb][2] *= a1; o[nb][3] *= a1;
        }

        // ---- O += P V ----
        #pragma unroll
        for (int kb = 0; kb < 4; kb++) {
            __half2 p0 = __floats2half2_rn(s[2*kb][0],   s[2*kb][1]);
            __half2 p1 = __floats2half2_rn(s[2*kb][2],   s[2*kb][3]);
            __half2 p2 = __floats2half2_rn(s[2*kb+1][0], s[2*kb+1][1]);
            __half2 p3 = __floats2half2_rn(s[2*kb+1][2], s[2*kb+1][3]);
            uint32_t ph[4] = { *(uint32_t*)&p0, *(uint32_t*)&p1,
                               *(uint32_t*)&p2, *(uint32_t*)&p3 };
            #pragma unroll
            for (int nb = 0; nb < 8; nb++) {
                uint32_t off = (kb * 16 + (lane & 15)) * FSTR + nb * 16;
                uint32_t v0, v1;
                LDSM_X2T(v0, v1, Vh + off);
                MMA_F16(o[nb], ph, v0, v1);
            }
        }
    }

    // ---- epilogue: normalize, store fp16 ----
    float inv0 = 1.0f / l0, inv1 = 1.0f / l1;
    const size_t rbase = (size_t)(b * SS + q0 + row_loc0) * DD + h * DK + (lane & 3) * 2;
    #pragma unroll
    for (int nb = 0; nb < 8; nb++) {
        *(__half2*)(o16 + rbase + nb * 8) =
            __floats2half2_rn(o[nb][0] * inv0, o[nb][1] * inv0);
        *(__half2*)(o16 + rbase + 8 * DD + nb * 8) =
            __floats2half2_rn(o[nb][2] * inv1, o[nb][3] * inv1);
    }
}

// ---------------- launch -----------------------------------------------------
extern "C" void kernel_launch(void* const* d_in, const int* in_sizes, int n_in,
                              void* d_out, int out_size)
{
    const float* Q  = (const float*)d_in[0];
    const float* K  = (const float*)d_in[1];
    const float* V  = (const float*)d_in[2];
    // d_in[3] = mask (causal by construction; handled analytically)
    const float* Wq = (const float*)d_in[4];
    const float* bq = (const float*)d_in[5];
    const float* Wk = (const float*)d_in[6];
    const float* bk = (const float*)d_in[7];
    const float* Wv = (const float*)d_in[8];
    const float* bv = (const float*)d_in[9];
    const float* Wo = (const float*)d_in[10];
    const float* bo = (const float*)d_in[11];

    __half *a16, *w16, *q16, *k16, *v16;
    cudaGetSymbolAddress((void**)&a16, g_a16);
    cudaGetSymbolAddress((void**)&w16, g_w16);
    cudaGetSymbolAddress((void**)&q16, g_q16);
    cudaGetSymbolAddress((void**)&k16, g_k16);
    cudaGetSymbolAddress((void**)&v16, g_v16);

    cudaFuncSetAttribute(gemm_mma,  cudaFuncAttributeMaxDynamicSharedMemorySize, GEMM_SMEM);
    cudaFuncSetAttribute(flash_mma, cudaFuncAttributeMaxDynamicSharedMemorySize, FLASH_SMEM);

    const int nAct4 = MR * DD / 4;
    const int nW4   = DD * DD / 4;
    dim3 gemmGrid(DD / 128, MR / 128);

    // Q projection (score scale 1/8 folded into epilogue, incl. bias)
    conv_f16<<<(nAct4 + 255) / 256, 256>>>(Q, a16, nAct4);
    conv_f16<<<(nW4 + 255) / 256, 256>>>(Wq, w16, nW4);
    gemm_mma<<<gemmGrid, 256, GEMM_SMEM>>>(a16, w16, bq, nullptr, q16, 0.125f);
    // K projection
    conv_f16<<<(nAct4 + 255) / 256, 256>>>(K, a16, nAct4);
    conv_f16<<<(nW4 + 255) / 256, 256>>>(Wk, w16, nW4);
    gemm_mma<<<gemmGrid, 256, GEMM_SMEM>>>(a16, w16, bk, nullptr, k16, 1.0f);
    // V projection
    conv_f16<<<(nAct4 + 255) / 256, 256>>>(V, a16, nAct4);
    conv_f16<<<(nW4 + 255) / 256, 256>>>(Wv, w16, nW4);
    gemm_mma<<<gemmGrid, 256, GEMM_SMEM>>>(a16, w16, bv, nullptr, v16, 1.0f);

    // attention (single-pass fp16; O written into a16)
    dim3 attnGrid(SS / 64, BB * HH);
    flash_mma<<<attnGrid, 128, FLASH_SMEM>>>(q16, k16, v16, a16);

    // output projection (fp32 out)
    conv_f16<<<(nW4 + 255) / 256, 256>>>(Wo, w16, nW4);
    gemm_mma<<<gemmGrid, 256, GEMM_SMEM>>>(a16, w16, bo, (float*)d_out, nullptr, 1.0f);
}